// round 1
// baseline (speedup 1.0000x reference)
#include <cuda_runtime.h>
#include <math.h>

// ---------------- problem constants ----------------
#define ROWS   65536      // B*H*W tokens
#define CDIM   512
#define QKVC   1536
#define NHEAD  16
#define HD     32
#define NTOK   64         // tokens per "window" (= one image row of 64 px)
#define BWIN   1024       // B_ = B * nWs
// ----------------------------------------------------

// Scratch (device globals: allocation-free)
__device__ __align__(16) float g_qkv[(size_t)ROWS * QKVC];   // 402 MB
__device__ __align__(16) float g_A[(size_t)ROWS * 1024];     // 268 MB: [fine | coarse] concat
__device__ __align__(16) float g_Kg[16 * 16 * 64 * 32];      // pooled K: [b][h][w][d]
__device__ __align__(16) float g_Vg[16 * 16 * 64 * 32];
__device__ __align__(16) float g_W[1024 * 512];              // combined projection weight
__device__ __align__(16) float g_bc[512];                    // combined bias

// ============================================================
// Generic tiled FP32 GEMM: C = A(MxK) @ B(KxN) (+ bias), row-major.
// 128x128 block tile, BK=8, 256 threads, 8x8 accum per thread.
// All problem dims here are multiples of 128 (M) / 128 (N) / 8 (K).
// ============================================================
__global__ __launch_bounds__(256) void gemm128(
    const float* __restrict__ A, const float* __restrict__ Bm,
    const float* __restrict__ bias, float* __restrict__ Cm,
    int M, int Nn, int K)
{
    __shared__ float As[8][128];   // transposed A tile
    __shared__ float Bs[8][128];

    const int t  = threadIdx.x;
    const int m0 = blockIdx.y * 128;
    const int n0 = blockIdx.x * 128;

    const int ar = t >> 1, ac = (t & 1) * 4;   // A tile load: 128 rows x 8 cols
    const int br = t >> 5, bc = (t & 31) * 4;  // B tile load: 8 rows x 128 cols
    const int ty = t >> 4, tx = t & 15;        // 16x16 thread grid, 8x8 each

    float acc[8][8];
#pragma unroll
    for (int i = 0; i < 8; i++)
#pragma unroll
        for (int j = 0; j < 8; j++) acc[i][j] = 0.f;

    const float* Aptr = A + (size_t)(m0 + ar) * K + ac;
    const float* Bptr = Bm + (size_t)br * Nn + n0 + bc;

    for (int k0 = 0; k0 < K; k0 += 8) {
        float4 av = *(const float4*)(Aptr + k0);
        float4 bv = *(const float4*)(Bptr + (size_t)k0 * Nn);
        __syncthreads();
        As[ac + 0][ar] = av.x;
        As[ac + 1][ar] = av.y;
        As[ac + 2][ar] = av.z;
        As[ac + 3][ar] = av.w;
        *(float4*)&Bs[br][bc] = bv;
        __syncthreads();
#pragma unroll
        for (int kk = 0; kk < 8; kk++) {
            float ra[8], rb[8];
#pragma unroll
            for (int i = 0; i < 8; i++) ra[i] = As[kk][ty * 8 + i];
#pragma unroll
            for (int j = 0; j < 8; j++) rb[j] = Bs[kk][tx * 8 + j];
#pragma unroll
            for (int i = 0; i < 8; i++)
#pragma unroll
                for (int j = 0; j < 8; j++) acc[i][j] += ra[i] * rb[j];
        }
    }

    float bj[8];
#pragma unroll
    for (int j = 0; j < 8; j++) bj[j] = bias ? bias[n0 + tx * 8 + j] : 0.f;

#pragma unroll
    for (int i = 0; i < 8; i++) {
        float* crow = Cm + (size_t)(m0 + ty * 8 + i) * Nn + n0 + tx * 8;
        float4 v0, v1;
        v0.x = acc[i][0] + bj[0]; v0.y = acc[i][1] + bj[1];
        v0.z = acc[i][2] + bj[2]; v0.w = acc[i][3] + bj[3];
        v1.x = acc[i][4] + bj[4]; v1.y = acc[i][5] + bj[5];
        v1.z = acc[i][6] + bj[6]; v1.w = acc[i][7] + bj[7];
        *(float4*)crow       = v0;
        *(float4*)(crow + 4) = v1;
    }
}

// ============================================================
// Pooled K/V: g_Kg[b][h][w][d] = sum_n K[(b*64+w)*64+n][h][d] * pool_w[n] + pool_b
// idx layout = ((b*16+h)*64+w)*32 + d  (matches g_Kg flat order)
// ============================================================
__global__ void pool_kernel(const float* __restrict__ pool_w,
                            const float* __restrict__ pool_b)
{
    int idx = blockIdx.x * 256 + threadIdx.x;   // 524288 total
    int d = idx & 31;
    int w = (idx >> 5) & 63;
    int h = (idx >> 11) & 15;
    int b = idx >> 15;
    const float* base = g_qkv + (size_t)((b * 64 + w) * 64) * QKVC + h * 32 + d;
    float sk = 0.f, sv = 0.f;
#pragma unroll 8
    for (int n = 0; n < 64; n++) {
        float pw = pool_w[n];
        sk += base[(size_t)n * QKVC + 512]  * pw;
        sv += base[(size_t)n * QKVC + 1024] * pw;
    }
    float pb = pool_b[0];
    g_Kg[idx] = sk + pb;
    g_Vg[idx] = sv + pb;
}

// ============================================================
// Combined bias: bc[j] = pfc_b[j] + sum_c lpb[c]*pfw[c][j] + sum_c gpb[c]*pfw[512+c][j]
// ============================================================
__global__ void bias_comb(const float* __restrict__ lpb, const float* __restrict__ gpb,
                          const float* __restrict__ pfw, const float* __restrict__ pfb)
{
    int j = blockIdx.x * 256 + threadIdx.x;
    if (j >= 512) return;
    float s = pfb[j];
    for (int c = 0; c < 512; c++) s += lpb[c] * pfw[c * 512 + j];
    for (int c = 0; c < 512; c++) s += gpb[c] * pfw[(512 + c) * 512 + j];
    g_bc[j] = s;
}

// ============================================================
// Fused fine + coarse attention. One block per (head, window b_).
// 256 threads: 4 threads per query row (n = t/4), each handles 16 score
// cols / 8 output dims. Writes into the concat buffer g_A.
// ============================================================
__global__ __launch_bounds__(256) void attn_kernel(const float* __restrict__ lbt,
                                                   const float* __restrict__ gbt)
{
    const int head = blockIdx.x;
    const int bw   = blockIdx.y;          // b_
    const int b    = bw >> 6;
    const int t    = threadIdx.x;

    __shared__ float sq[64][33], sk[64][33], sv[64][33];
    __shared__ float S[64][65];
    __shared__ float tabL[225], tabG[225];

    for (int i = t; i < 225; i += 256) {
        tabL[i] = lbt[i * 16 + head];
        tabG[i] = gbt[i * 16 + head];
    }

    // load q,k,v tiles (64x32 each) from g_qkv
    {
        const float* qbase = g_qkv + (size_t)(bw * 64) * QKVC + head * 32;
        for (int i = t; i < 512; i += 256) {
            int n = i >> 3, d = (i & 7) * 4;
            float4 q4 = *(const float4*)(qbase + (size_t)n * QKVC + d);
            float4 k4 = *(const float4*)(qbase + (size_t)n * QKVC + 512 + d);
            float4 v4 = *(const float4*)(qbase + (size_t)n * QKVC + 1024 + d);
            sq[n][d] = q4.x; sq[n][d+1] = q4.y; sq[n][d+2] = q4.z; sq[n][d+3] = q4.w;
            sk[n][d] = k4.x; sk[n][d+1] = k4.y; sk[n][d+2] = k4.z; sk[n][d+3] = k4.w;
            sv[n][d] = v4.x; sv[n][d+1] = v4.y; sv[n][d+2] = v4.z; sv[n][d+3] = v4.w;
        }
    }
    __syncthreads();

    const int n  = t >> 2;
    const int gl = t & 3;
    const int ri = n >> 3, ci = n & 7;
    const int dbase = gl * 8;

    float qr[32];
#pragma unroll
    for (int d = 0; d < 32; d++) qr[d] = sq[n][d] * 0.17677669529663687f; // 1/sqrt(32)

    // -------- fine attention --------
    {
        float sc[16], mx = -1e30f;
#pragma unroll
        for (int i = 0; i < 16; i++) {
            int m = gl + i * 4;
            float a = 0.f;
#pragma unroll
            for (int d = 0; d < 32; d++) a += qr[d] * sk[m][d];
            int rj = m >> 3, cj = m & 7;
            a += tabL[(ri - rj + 7) * 15 + (ci - cj + 7)];
            sc[i] = a;
            mx = fmaxf(mx, a);
        }
        mx = fmaxf(mx, __shfl_xor_sync(0xffffffffu, mx, 1));
        mx = fmaxf(mx, __shfl_xor_sync(0xffffffffu, mx, 2));
        float sum = 0.f;
#pragma unroll
        for (int i = 0; i < 16; i++) {
            float e = expf(sc[i] - mx);
            S[n][gl + i * 4] = e;
            sum += e;
        }
        sum += __shfl_xor_sync(0xffffffffu, sum, 1);
        sum += __shfl_xor_sync(0xffffffffu, sum, 2);
        float inv = 1.f / sum;
        __syncwarp();

        float acc[8];
#pragma unroll
        for (int j = 0; j < 8; j++) acc[j] = 0.f;
        for (int m = 0; m < 64; m++) {
            float p = S[n][m];
#pragma unroll
            for (int j = 0; j < 8; j++) acc[j] += p * sv[m][dbase + j];
        }
        float* orow = g_A + (size_t)(bw * 64 + n) * 1024 + head * 32 + dbase;
#pragma unroll
        for (int j = 0; j < 8; j++) orow[j] = acc[j] * inv;
    }
    __syncthreads();   // everyone done with sk/sv before overwrite

    // reload sk/sv with pooled Kg/Vg for this (b, head)
    {
        const float* kgb = g_Kg + (size_t)((b * 16 + head) * 64) * 32;
        const float* vgb = g_Vg + (size_t)((b * 16 + head) * 64) * 32;
        for (int i = t; i < 512; i += 256) {
            int w = i >> 3, d = (i & 7) * 4;
            float4 k4 = *(const float4*)(kgb + w * 32 + d);
            float4 v4 = *(const float4*)(vgb + w * 32 + d);
            sk[w][d] = k4.x; sk[w][d+1] = k4.y; sk[w][d+2] = k4.z; sk[w][d+3] = k4.w;
            sv[w][d] = v4.x; sv[w][d+1] = v4.y; sv[w][d+2] = v4.z; sv[w][d+3] = v4.w;
        }
    }
    __syncthreads();

    // -------- coarse attention --------
    {
        float sc[16], mx = -1e30f;
#pragma unroll
        for (int i = 0; i < 16; i++) {
            int w = gl + i * 4;
            float a = 0.f;
#pragma unroll
            for (int d = 0; d < 32; d++) a += qr[d] * sk[w][d];
            int wr = w >> 3, wc = w & 7;
            a += tabG[(ri - wr + 7) * 15 + (ci - wc + 7)];
            sc[i] = a;
            mx = fmaxf(mx, a);
        }
        mx = fmaxf(mx, __shfl_xor_sync(0xffffffffu, mx, 1));
        mx = fmaxf(mx, __shfl_xor_sync(0xffffffffu, mx, 2));
        float sum = 0.f;
#pragma unroll
        for (int i = 0; i < 16; i++) {
            float e = expf(sc[i] - mx);
            S[n][gl + i * 4] = e;
            sum += e;
        }
        sum += __shfl_xor_sync(0xffffffffu, sum, 1);
        sum += __shfl_xor_sync(0xffffffffu, sum, 2);
        float inv = 1.f / sum;
        __syncwarp();

        float acc[8];
#pragma unroll
        for (int j = 0; j < 8; j++) acc[j] = 0.f;
        for (int m = 0; m < 64; m++) {
            float p = S[n][m];
#pragma unroll
            for (int j = 0; j < 8; j++) acc[j] += p * sv[m][dbase + j];
        }
        float* orow = g_A + (size_t)(bw * 64 + n) * 1024 + 512 + head * 32 + dbase;
#pragma unroll
        for (int j = 0; j < 8; j++) orow[j] = acc[j] * inv;
    }
}

// ============================================================
// launch
// ============================================================
extern "C" void kernel_launch(void* const* d_in, const int* in_sizes, int n_in,
                              void* d_out, int out_size)
{
    (void)in_sizes; (void)n_in; (void)out_size;
    const float* x     = (const float*)d_in[0];
    const float* qkv_w = (const float*)d_in[1];
    const float* qkv_b = (const float*)d_in[2];
    const float* lbt   = (const float*)d_in[3];
    const float* gbt   = (const float*)d_in[4];
    const float* lpw   = (const float*)d_in[5];
    const float* lpb   = (const float*)d_in[6];
    const float* pw    = (const float*)d_in[7];
    const float* pb    = (const float*)d_in[8];
    const float* gpw   = (const float*)d_in[9];
    const float* gpb   = (const float*)d_in[10];
    const float* pfw   = (const float*)d_in[11];
    const float* pfb   = (const float*)d_in[12];
    float* out = (float*)d_out;

    float *gqkv, *gA, *gW, *gbc;
    cudaGetSymbolAddress((void**)&gqkv, g_qkv);
    cudaGetSymbolAddress((void**)&gA,   g_A);
    cudaGetSymbolAddress((void**)&gW,   g_W);
    cudaGetSymbolAddress((void**)&gbc,  g_bc);

    // combined projection weight: W = vstack(Wl @ pfw_top, Wg @ pfw_bot)
    gemm128<<<dim3(4, 4), 256>>>(lpw, pfw,               nullptr, gW,             512, 512, 512);
    gemm128<<<dim3(4, 4), 256>>>(gpw, pfw + 512 * 512,   nullptr, gW + 512 * 512, 512, 512, 512);
    bias_comb<<<2, 256>>>(lpb, gpb, pfw, pfb);

    // QKV projection
    gemm128<<<dim3(QKVC / 128, ROWS / 128), 256>>>(x, qkv_w, qkv_b, gqkv, ROWS, QKVC, CDIM);

    // pooled K/V
    pool_kernel<<<2048, 256>>>(pw, pb);

    // fused fine + coarse attention -> concat buffer
    attn_kernel<<<dim3(NHEAD, BWIN), 256>>>(lbt, gbt);

    // out = [A_f | A_c] @ W + bc
    gemm128<<<dim3(512 / 128, ROWS / 128), 256>>>(gA, gW, gbc, out, ROWS, 512, 1024);
}

// round 3
// speedup vs baseline: 1.7811x; 1.7811x over previous
#include <cuda_runtime.h>
#include <math.h>

// ---------------- problem constants ----------------
#define ROWS   65536      // B*H*W tokens
#define CDIM   512
#define QKVC   1536
#define NHEAD  16
#define BWIN   1024       // B_ = B * nWs
// ----------------------------------------------------

// Scratch (device globals: allocation-free)
__device__ __align__(16) float g_qkv[(size_t)ROWS * QKVC];   // 402 MB
__device__ __align__(16) float g_A[(size_t)ROWS * 1024];     // 268 MB: [fine | coarse] concat
__device__ __align__(16) float g_Kg[16 * 16 * 64 * 32];      // pooled K: [b][h][w][d]
__device__ __align__(16) float g_Vg[16 * 16 * 64 * 32];
__device__ __align__(16) float g_W[1024 * 512];              // combined projection weight
__device__ __align__(16) float g_bc[512];                    // combined bias

// tf32 round-to-nearest conversion: result is the tf32 bit-pattern in a b32 reg.
__device__ __forceinline__ float f2tf32(float x) {
    unsigned r;
    asm("cvt.rna.tf32.f32 %0, %1;" : "=r"(r) : "f"(x));
    return __uint_as_float(r);
}

// ============================================================
// TF32 tensor-core GEMM: C = A(MxK) @ B(KxN) (+ bias), fp32 row-major.
// 128x128 block tile, BK=16 double-buffered, 256 threads (8 warps),
// warp tile 64x32 via mma.sync.m16n8k8.tf32. Dims: M%128==0, N%128==0, K%16==0.
// ============================================================
__global__ __launch_bounds__(256) void gemm_tf32(
    const float* __restrict__ A, const float* __restrict__ Bm,
    const float* __restrict__ bias, float* __restrict__ Cm,
    int M, int N, int K)
{
    __shared__ float As[2][16][132];   // [buf][k][row(padded)]
    __shared__ float Bs[2][16][132];   // [buf][k][col(padded)]

    const int t    = threadIdx.x;
    const int m0   = blockIdx.y * 128;
    const int n0   = blockIdx.x * 128;
    const int warp = t >> 5, lane = t & 31;
    const int grp  = lane >> 2, tig = lane & 3;
    const int wm   = (warp & 1) * 64;     // warp row offset in tile
    const int wn   = (warp >> 1) * 32;    // warp col offset in tile

    // global load mapping (each thread: 2 float4 from A, 2 from B per chunk)
    const int aRow0 = t >> 2;            // 0..63 ; +64 for second
    const int aCol  = (t & 3) * 4;       // 0,4,8,12
    const int bK0   = t >> 5;            // 0..7 ; +8 for second
    const int bCol  = (t & 31) * 4;      // 0..124

    const float* aP0 = A  + (size_t)(m0 + aRow0)      * K + aCol;
    const float* aP1 = A  + (size_t)(m0 + aRow0 + 64) * K + aCol;
    const float* bP0 = Bm + (size_t)bK0       * N + n0 + bCol;
    const float* bP1 = Bm + (size_t)(bK0 + 8) * N + n0 + bCol;

    float acc[4][4][4];
#pragma unroll
    for (int mi = 0; mi < 4; mi++)
#pragma unroll
        for (int ni = 0; ni < 4; ni++)
#pragma unroll
            for (int r = 0; r < 4; r++) acc[mi][ni][r] = 0.f;

    const int nk = K >> 4;
    float4 aReg[2], bReg[2];

    // ---- prefetch chunk 0 ----
    aReg[0] = *(const float4*)(aP0);
    aReg[1] = *(const float4*)(aP1);
    bReg[0] = *(const float4*)(bP0);
    bReg[1] = *(const float4*)(bP1);
    {
        As[0][aCol + 0][aRow0] = f2tf32(aReg[0].x);  As[0][aCol + 1][aRow0] = f2tf32(aReg[0].y);
        As[0][aCol + 2][aRow0] = f2tf32(aReg[0].z);  As[0][aCol + 3][aRow0] = f2tf32(aReg[0].w);
        As[0][aCol + 0][aRow0 + 64] = f2tf32(aReg[1].x);  As[0][aCol + 1][aRow0 + 64] = f2tf32(aReg[1].y);
        As[0][aCol + 2][aRow0 + 64] = f2tf32(aReg[1].z);  As[0][aCol + 3][aRow0 + 64] = f2tf32(aReg[1].w);
        float4 c0, c1;
        c0.x = f2tf32(bReg[0].x); c0.y = f2tf32(bReg[0].y);
        c0.z = f2tf32(bReg[0].z); c0.w = f2tf32(bReg[0].w);
        c1.x = f2tf32(bReg[1].x); c1.y = f2tf32(bReg[1].y);
        c1.z = f2tf32(bReg[1].z); c1.w = f2tf32(bReg[1].w);
        *(float4*)&Bs[0][bK0][bCol]     = c0;
        *(float4*)&Bs[0][bK0 + 8][bCol] = c1;
    }
    __syncthreads();

    for (int kc = 0; kc < nk; kc++) {
        const int buf = kc & 1;
        const bool has = (kc + 1) < nk;
        if (has) {
            const int ko = (kc + 1) * 16;
            aReg[0] = *(const float4*)(aP0 + ko);
            aReg[1] = *(const float4*)(aP1 + ko);
            bReg[0] = *(const float4*)(bP0 + (size_t)ko * N);
            bReg[1] = *(const float4*)(bP1 + (size_t)ko * N);
        }

        // ---- compute from smem[buf] ----
#pragma unroll
        for (int ks = 0; ks < 2; ks++) {
            const int km = ks * 8;
            float a[4][4], b[4][2];
#pragma unroll
            for (int mi = 0; mi < 4; mi++) {
                const int rr = wm + mi * 16 + grp;
                a[mi][0] = As[buf][km + tig][rr];
                a[mi][1] = As[buf][km + tig][rr + 8];
                a[mi][2] = As[buf][km + tig + 4][rr];
                a[mi][3] = As[buf][km + tig + 4][rr + 8];
            }
#pragma unroll
            for (int ni = 0; ni < 4; ni++) {
                const int cc = wn + ni * 8 + grp;
                b[ni][0] = Bs[buf][km + tig][cc];
                b[ni][1] = Bs[buf][km + tig + 4][cc];
            }
#pragma unroll
            for (int mi = 0; mi < 4; mi++)
#pragma unroll
                for (int ni = 0; ni < 4; ni++) {
                    asm volatile(
                        "mma.sync.aligned.m16n8k8.row.col.f32.tf32.tf32.f32 "
                        "{%0,%1,%2,%3},{%4,%5,%6,%7},{%8,%9},{%0,%1,%2,%3};"
                        : "+f"(acc[mi][ni][0]), "+f"(acc[mi][ni][1]),
                          "+f"(acc[mi][ni][2]), "+f"(acc[mi][ni][3])
                        : "r"(__float_as_uint(a[mi][0])), "r"(__float_as_uint(a[mi][1])),
                          "r"(__float_as_uint(a[mi][2])), "r"(__float_as_uint(a[mi][3])),
                          "r"(__float_as_uint(b[ni][0])), "r"(__float_as_uint(b[ni][1])));
                }
        }

        if (has) {
            const int bb = buf ^ 1;
            As[bb][aCol + 0][aRow0] = f2tf32(aReg[0].x);  As[bb][aCol + 1][aRow0] = f2tf32(aReg[0].y);
            As[bb][aCol + 2][aRow0] = f2tf32(aReg[0].z);  As[bb][aCol + 3][aRow0] = f2tf32(aReg[0].w);
            As[bb][aCol + 0][aRow0 + 64] = f2tf32(aReg[1].x);  As[bb][aCol + 1][aRow0 + 64] = f2tf32(aReg[1].y);
            As[bb][aCol + 2][aRow0 + 64] = f2tf32(aReg[1].z);  As[bb][aCol + 3][aRow0 + 64] = f2tf32(aReg[1].w);
            float4 c0, c1;
            c0.x = f2tf32(bReg[0].x); c0.y = f2tf32(bReg[0].y);
            c0.z = f2tf32(bReg[0].z); c0.w = f2tf32(bReg[0].w);
            c1.x = f2tf32(bReg[1].x); c1.y = f2tf32(bReg[1].y);
            c1.z = f2tf32(bReg[1].z); c1.w = f2tf32(bReg[1].w);
            *(float4*)&Bs[bb][bK0][bCol]     = c0;
            *(float4*)&Bs[bb][bK0 + 8][bCol] = c1;
        }
        __syncthreads();
    }

    // ---- epilogue ----
#pragma unroll
    for (int ni = 0; ni < 4; ni++) {
        const int col = n0 + wn + ni * 8 + tig * 2;
        float b0 = bias ? bias[col]     : 0.f;
        float b1 = bias ? bias[col + 1] : 0.f;
#pragma unroll
        for (int mi = 0; mi < 4; mi++) {
            const int row = m0 + wm + mi * 16 + grp;
            float2 v0, v1;
            v0.x = acc[mi][ni][0] + b0;  v0.y = acc[mi][ni][1] + b1;
            v1.x = acc[mi][ni][2] + b0;  v1.y = acc[mi][ni][3] + b1;
            *(float2*)(Cm + (size_t)row * N + col)       = v0;
            *(float2*)(Cm + (size_t)(row + 8) * N + col) = v1;
        }
    }
}

// ============================================================
// Pooled K/V: g_Kg[b][h][w][d] = sum_n K[(b*64+w)*64+n][h][d] * pool_w[n] + pool_b
// ============================================================
__global__ void pool_kernel(const float* __restrict__ pool_w,
                            const float* __restrict__ pool_b)
{
    int idx = blockIdx.x * 256 + threadIdx.x;   // 524288 total
    int d = idx & 31;
    int w = (idx >> 5) & 63;
    int h = (idx >> 11) & 15;
    int b = idx >> 15;
    const float* base = g_qkv + (size_t)((b * 64 + w) * 64) * QKVC + h * 32 + d;
    float sk = 0.f, sv = 0.f;
#pragma unroll 8
    for (int n = 0; n < 64; n++) {
        float pw = pool_w[n];
        sk += base[(size_t)n * QKVC + 512]  * pw;
        sv += base[(size_t)n * QKVC + 1024] * pw;
    }
    float pb = pool_b[0];
    g_Kg[idx] = sk + pb;
    g_Vg[idx] = sv + pb;
}

// ============================================================
// Combined bias
// ============================================================
__global__ void bias_comb(const float* __restrict__ lpb, const float* __restrict__ gpb,
                          const float* __restrict__ pfw, const float* __restrict__ pfb)
{
    int j = blockIdx.x * 256 + threadIdx.x;
    if (j >= 512) return;
    float s = pfb[j];
    for (int c = 0; c < 512; c++) s += lpb[c] * pfw[c * 512 + j];
    for (int c = 0; c < 512; c++) s += gpb[c] * pfw[(512 + c) * 512 + j];
    g_bc[j] = s;
}

// ============================================================
// Fused fine + coarse attention. One block per (head, window b_).
// ============================================================
__global__ __launch_bounds__(256) void attn_kernel(const float* __restrict__ lbt,
                                                   const float* __restrict__ gbt)
{
    const int head = blockIdx.x;
    const int bw   = blockIdx.y;          // b_
    const int b    = bw >> 6;
    const int t    = threadIdx.x;

    __shared__ float sq[64][33], sk[64][33], sv[64][33];
    __shared__ float S[64][65];
    __shared__ float tabL[225], tabG[225];

    for (int i = t; i < 225; i += 256) {
        tabL[i] = lbt[i * 16 + head];
        tabG[i] = gbt[i * 16 + head];
    }

    {
        const float* qbase = g_qkv + (size_t)(bw * 64) * QKVC + head * 32;
        for (int i = t; i < 512; i += 256) {
            int n = i >> 3, d = (i & 7) * 4;
            float4 q4 = *(const float4*)(qbase + (size_t)n * QKVC + d);
            float4 k4 = *(const float4*)(qbase + (size_t)n * QKVC + 512 + d);
            float4 v4 = *(const float4*)(qbase + (size_t)n * QKVC + 1024 + d);
            sq[n][d] = q4.x; sq[n][d+1] = q4.y; sq[n][d+2] = q4.z; sq[n][d+3] = q4.w;
            sk[n][d] = k4.x; sk[n][d+1] = k4.y; sk[n][d+2] = k4.z; sk[n][d+3] = k4.w;
            sv[n][d] = v4.x; sv[n][d+1] = v4.y; sv[n][d+2] = v4.z; sv[n][d+3] = v4.w;
        }
    }
    __syncthreads();

    const int n  = t >> 2;
    const int gl = t & 3;
    const int ri = n >> 3, ci = n & 7;
    const int dbase = gl * 8;

    float qr[32];
#pragma unroll
    for (int d = 0; d < 32; d++) qr[d] = sq[n][d] * 0.17677669529663687f; // 1/sqrt(32)

    // -------- fine attention --------
    {
        float sc[16], mx = -1e30f;
#pragma unroll
        for (int i = 0; i < 16; i++) {
            int m = gl + i * 4;
            float a = 0.f;
#pragma unroll
            for (int d = 0; d < 32; d++) a += qr[d] * sk[m][d];
            int rj = m >> 3, cj = m & 7;
            a += tabL[(ri - rj + 7) * 15 + (ci - cj + 7)];
            sc[i] = a;
            mx = fmaxf(mx, a);
        }
        mx = fmaxf(mx, __shfl_xor_sync(0xffffffffu, mx, 1));
        mx = fmaxf(mx, __shfl_xor_sync(0xffffffffu, mx, 2));
        float sum = 0.f;
#pragma unroll
        for (int i = 0; i < 16; i++) {
            float e = expf(sc[i] - mx);
            S[n][gl + i * 4] = e;
            sum += e;
        }
        sum += __shfl_xor_sync(0xffffffffu, sum, 1);
        sum += __shfl_xor_sync(0xffffffffu, sum, 2);
        float inv = 1.f / sum;
        __syncwarp();

        float acc[8];
#pragma unroll
        for (int j = 0; j < 8; j++) acc[j] = 0.f;
        for (int m = 0; m < 64; m++) {
            float p = S[n][m];
#pragma unroll
            for (int j = 0; j < 8; j++) acc[j] += p * sv[m][dbase + j];
        }
        float* orow = g_A + (size_t)(bw * 64 + n) * 1024 + head * 32 + dbase;
#pragma unroll
        for (int j = 0; j < 8; j++) orow[j] = acc[j] * inv;
    }
    __syncthreads();

    {
        const float* kgb = g_Kg + (size_t)((b * 16 + head) * 64) * 32;
        const float* vgb = g_Vg + (size_t)((b * 16 + head) * 64) * 32;
        for (int i = t; i < 512; i += 256) {
            int w = i >> 3, d = (i & 7) * 4;
            float4 k4 = *(const float4*)(kgb + w * 32 + d);
            float4 v4 = *(const float4*)(vgb + w * 32 + d);
            sk[w][d] = k4.x; sk[w][d+1] = k4.y; sk[w][d+2] = k4.z; sk[w][d+3] = k4.w;
            sv[w][d] = v4.x; sv[w][d+1] = v4.y; sv[w][d+2] = v4.z; sv[w][d+3] = v4.w;
        }
    }
    __syncthreads();

    // -------- coarse attention --------
    {
        float sc[16], mx = -1e30f;
#pragma unroll
        for (int i = 0; i < 16; i++) {
            int w = gl + i * 4;
            float a = 0.f;
#pragma unroll
            for (int d = 0; d < 32; d++) a += qr[d] * sk[w][d];
            int wr = w >> 3, wc = w & 7;
            a += tabG[(ri - wr + 7) * 15 + (ci - wc + 7)];
            sc[i] = a;
            mx = fmaxf(mx, a);
        }
        mx = fmaxf(mx, __shfl_xor_sync(0xffffffffu, mx, 1));
        mx = fmaxf(mx, __shfl_xor_sync(0xffffffffu, mx, 2));
        float sum = 0.f;
#pragma unroll
        for (int i = 0; i < 16; i++) {
            float e = expf(sc[i] - mx);
            S[n][gl + i * 4] = e;
            sum += e;
        }
        sum += __shfl_xor_sync(0xffffffffu, sum, 1);
        sum += __shfl_xor_sync(0xffffffffu, sum, 2);
        float inv = 1.f / sum;
        __syncwarp();

        float acc[8];
#pragma unroll
        for (int j = 0; j < 8; j++) acc[j] = 0.f;
        for (int m = 0; m < 64; m++) {
            float p = S[n][m];
#pragma unroll
            for (int j = 0; j < 8; j++) acc[j] += p * sv[m][dbase + j];
        }
        float* orow = g_A + (size_t)(bw * 64 + n) * 1024 + 512 + head * 32 + dbase;
#pragma unroll
        for (int j = 0; j < 8; j++) orow[j] = acc[j] * inv;
    }
}

// ============================================================
// launch
// ============================================================
extern "C" void kernel_launch(void* const* d_in, const int* in_sizes, int n_in,
                              void* d_out, int out_size)
{
    (void)in_sizes; (void)n_in; (void)out_size;
    const float* x     = (const float*)d_in[0];
    const float* qkv_w = (const float*)d_in[1];
    const float* qkv_b = (const float*)d_in[2];
    const float* lbt   = (const float*)d_in[3];
    const float* gbt   = (const float*)d_in[4];
    const float* lpw   = (const float*)d_in[5];
    const float* lpb   = (const float*)d_in[6];
    const float* pw    = (const float*)d_in[7];
    const float* pb    = (const float*)d_in[8];
    const float* gpw   = (const float*)d_in[9];
    const float* gpb   = (const float*)d_in[10];
    const float* pfw   = (const float*)d_in[11];
    const float* pfb   = (const float*)d_in[12];
    float* out = (float*)d_out;

    float *gqkv, *gA, *gW, *gbc;
    cudaGetSymbolAddress((void**)&gqkv, g_qkv);
    cudaGetSymbolAddress((void**)&gA,   g_A);
    cudaGetSymbolAddress((void**)&gW,   g_W);
    cudaGetSymbolAddress((void**)&gbc,  g_bc);

    // combined projection weight: W = vstack(Wl @ pfw_top, Wg @ pfw_bot)
    gemm_tf32<<<dim3(4, 4), 256>>>(lpw, pfw,             nullptr, gW,             512, 512, 512);
    gemm_tf32<<<dim3(4, 4), 256>>>(gpw, pfw + 512 * 512, nullptr, gW + 512 * 512, 512, 512, 512);
    bias_comb<<<2, 256>>>(lpb, gpb, pfw, pfb);

    // QKV projection
    gemm_tf32<<<dim3(QKVC / 128, ROWS / 128), 256>>>(x, qkv_w, qkv_b, gqkv, ROWS, QKVC, CDIM);

    // pooled K/V
    pool_kernel<<<2048, 256>>>(pw, pb);

    // fused fine + coarse attention -> concat buffer
    attn_kernel<<<dim3(NHEAD, BWIN), 256>>>(lbt, gbt);

    // out = [A_f | A_c] @ W + bc
    gemm_tf32<<<dim3(512 / 128, ROWS / 128), 256>>>(gA, gW, gbc, out, ROWS, 512, 1024);
}

// round 5
// speedup vs baseline: 2.1123x; 1.1859x over previous
#include <cuda_runtime.h>
#include <math.h>
#include <stdint.h>

// ---------------- problem constants ----------------
#define ROWS   65536
#define CDIM   512
#define QKVC   1536
#define NHEAD  16
#define BWIN   1024
// ----------------------------------------------------

// Scratch (device globals: allocation-free)
__device__ __align__(16) float g_qkv[(size_t)ROWS * QKVC];
__device__ __align__(16) float g_A[(size_t)ROWS * 1024];
__device__ __align__(16) float g_xr[(size_t)ROWS * CDIM];     // tf32-rounded x
__device__ __align__(16) float g_Kg[16 * 16 * 64 * 32];
__device__ __align__(16) float g_Vg[16 * 16 * 64 * 32];
__device__ __align__(16) float g_W[1024 * 512];
__device__ __align__(16) float g_WT[512 * 1024];              // W^T [n][k], tf32-rounded
__device__ __align__(16) float g_qwT[QKVC * CDIM];            // qkv_w^T [n][k], tf32-rounded
__device__ __align__(16) float g_bc[512];

__device__ __forceinline__ float f2tf32(float x) {
    unsigned r;
    asm("cvt.rna.tf32.f32 %0, %1;" : "=r"(r) : "f"(x));
    return __uint_as_float(r);
}
__device__ __forceinline__ uint32_t smem_u32(const void* p) {
    uint32_t a;
    asm("{ .reg .u64 t; cvta.to.shared.u64 t, %1; cvt.u32.u64 %0, t; }" : "=r"(a) : "l"(p));
    return a;
}
#define CP_ASYNC16(dst, src) asm volatile("cp.async.cg.shared.global [%0], [%1], 16;" :: "r"(dst), "l"(src))
#define CP_COMMIT()          asm volatile("cp.async.commit_group;" ::: "memory")
#define CP_WAIT1()           asm volatile("cp.async.wait_group 1;" ::: "memory")

#define MMA_TF32(acc, a, b) \
    asm volatile( \
        "mma.sync.aligned.m16n8k8.row.col.f32.tf32.tf32.f32 " \
        "{%0,%1,%2,%3},{%4,%5,%6,%7},{%8,%9},{%0,%1,%2,%3};" \
        : "+f"((acc)[0]), "+f"((acc)[1]), "+f"((acc)[2]), "+f"((acc)[3]) \
        : "r"(__float_as_uint((a)[0])), "r"(__float_as_uint((a)[1])), \
          "r"(__float_as_uint((a)[2])), "r"(__float_as_uint((a)[3])), \
          "r"(__float_as_uint((b)[0])), "r"(__float_as_uint((b)[1])))

// ============================================================
// Main tensor GEMM: C = A(MxK) @ B^T (+bias), A row-major [m][k],
// B stored K-major [n][k]; BOTH pre-rounded to tf32.
// Block 128x256, warp tile 64x64 (8 warps), BK=32, 2-stage cp.async.
// Smem rows padded to 36 floats -> conflict-free fragment loads.
// Requires M%128==0, N%256==0, K%32==0.
// ============================================================
#define GSTRIDE 36
#define GASZ    (128 * GSTRIDE)          // 4608 floats
#define GBSZ    (256 * GSTRIDE)          // 9216 floats
#define GSTG    (GASZ + GBSZ)            // 13824 floats per stage
#define GSMEM   (2 * GSTG * 4)           // 110592 bytes

__global__ __launch_bounds__(256) void gemm_big(
    const float* __restrict__ A, const float* __restrict__ B,
    const float* __restrict__ bias, float* __restrict__ C,
    int M, int N, int K)
{
    extern __shared__ float smemf[];
    const uint32_t sbu = smem_u32(smemf);

    const int tid  = threadIdx.x;
    const int warp = tid >> 5, lane = tid & 31;
    const int grp  = lane >> 2, tig = lane & 3;
    const int m0 = blockIdx.y * 128;
    const int n0 = blockIdx.x * 256;
    const int wm = (warp & 1) * 64;
    const int wn = (warp >> 1) * 64;

    const int lrow = tid >> 3;           // 0..31 (x8 = 256 rows per pass set)
    const int lc4  = (tid & 7) * 4;      // float offset 0..28

    float acc[4][8][4];
#pragma unroll
    for (int mi = 0; mi < 4; mi++)
#pragma unroll
        for (int ni = 0; ni < 8; ni++)
#pragma unroll
            for (int r = 0; r < 4; r++) acc[mi][ni][r] = 0.f;

    const int nk = K >> 5;

    auto load_stage = [&](int buf, int kc) {
        const float* Ab = A + (size_t)m0 * K + kc * 32;
        const float* Bb = B + (size_t)n0 * K + kc * 32;
        const uint32_t sA = sbu + (uint32_t)(buf * GSTG) * 4;
        const uint32_t sB = sA + GASZ * 4;
        // A: 128 rows x 2 chunks-of-16B-groups (1024 cp / 256 thr = 4 each)
#pragma unroll
        for (int i = 0; i < 4; i++) {
            int row = lrow + i * 32;
            CP_ASYNC16(sA + (uint32_t)(row * GSTRIDE + lc4) * 4,
                       Ab + (size_t)row * K + lc4);
        }
        // B: 256 rows (2048 cp / 256 thr = 8 each)
#pragma unroll
        for (int i = 0; i < 8; i++) {
            int row = lrow + i * 32;
            CP_ASYNC16(sB + (uint32_t)(row * GSTRIDE + lc4) * 4,
                       Bb + (size_t)row * K + lc4);
        }
    };

    load_stage(0, 0); CP_COMMIT();
    if (nk > 1) load_stage(1, 1);
    CP_COMMIT();

    for (int kc = 0; kc < nk; kc++) {
        const int buf = kc & 1;
        CP_WAIT1();
        __syncthreads();

        const float* sA = smemf + buf * GSTG;
        const float* sB = sA + GASZ;
#pragma unroll
        for (int ks = 0; ks < 4; ks++) {
            const int km = ks * 8;
            float a[4][4], b[8][2];
#pragma unroll
            for (int mi = 0; mi < 4; mi++) {
                const int r = wm + mi * 16 + grp;
                a[mi][0] = sA[r * GSTRIDE + km + tig];
                a[mi][1] = sA[(r + 8) * GSTRIDE + km + tig];
                a[mi][2] = sA[r * GSTRIDE + km + tig + 4];
                a[mi][3] = sA[(r + 8) * GSTRIDE + km + tig + 4];
            }
#pragma unroll
            for (int ni = 0; ni < 8; ni++) {
                const int c = wn + ni * 8 + grp;
                b[ni][0] = sB[c * GSTRIDE + km + tig];
                b[ni][1] = sB[c * GSTRIDE + km + tig + 4];
            }
#pragma unroll
            for (int mi = 0; mi < 4; mi++)
#pragma unroll
                for (int ni = 0; ni < 8; ni++)
                    MMA_TF32(acc[mi][ni], a[mi], b[ni]);
        }
        __syncthreads();

        if (kc + 2 < nk) load_stage(buf, kc + 2);
        CP_COMMIT();
    }

    // ---- epilogue ----
#pragma unroll
    for (int ni = 0; ni < 8; ni++) {
        const int col = n0 + wn + ni * 8 + tig * 2;
        const float b0 = bias ? bias[col]     : 0.f;
        const float b1 = bias ? bias[col + 1] : 0.f;
#pragma unroll
        for (int mi = 0; mi < 4; mi++) {
            const int row = m0 + wm + mi * 16 + grp;
            float2 v0, v1;
            v0.x = acc[mi][ni][0] + b0;  v0.y = acc[mi][ni][1] + b1;
            v1.x = acc[mi][ni][2] + b0;  v1.y = acc[mi][ni][3] + b1;
            *(float2*)(C + (size_t)row * N + col)       = v0;
            *(float2*)(C + (size_t)(row + 8) * N + col) = v1;
        }
    }
}

// ============================================================
// legacy mma.sync tf32 GEMM (the two tiny 512^3 weight-prep GEMMs)
// B row-major [k][n] here.
// ============================================================
__global__ __launch_bounds__(256) void gemm_tf32(
    const float* __restrict__ A, const float* __restrict__ Bm,
    const float* __restrict__ bias, float* __restrict__ Cm,
    int M, int N, int K)
{
    __shared__ float As[2][16][132];
    __shared__ float Bs[2][16][132];

    const int t    = threadIdx.x;
    const int m0   = blockIdx.y * 128;
    const int n0   = blockIdx.x * 128;
    const int warp = t >> 5, lane = t & 31;
    const int grp  = lane >> 2, tig = lane & 3;
    const int wm   = (warp & 1) * 64;
    const int wn   = (warp >> 1) * 32;

    const int aRow0 = t >> 2;
    const int aCol  = (t & 3) * 4;
    const int bK0   = t >> 5;
    const int bCol  = (t & 31) * 4;

    const float* aP0 = A  + (size_t)(m0 + aRow0)      * K + aCol;
    const float* aP1 = A  + (size_t)(m0 + aRow0 + 64) * K + aCol;
    const float* bP0 = Bm + (size_t)bK0       * N + n0 + bCol;
    const float* bP1 = Bm + (size_t)(bK0 + 8) * N + n0 + bCol;

    float acc[4][4][4];
#pragma unroll
    for (int mi = 0; mi < 4; mi++)
#pragma unroll
        for (int ni = 0; ni < 4; ni++)
#pragma unroll
            for (int r = 0; r < 4; r++) acc[mi][ni][r] = 0.f;

    const int nk = K >> 4;
    float4 aReg[2], bReg[2];

    aReg[0] = *(const float4*)(aP0);
    aReg[1] = *(const float4*)(aP1);
    bReg[0] = *(const float4*)(bP0);
    bReg[1] = *(const float4*)(bP1);
    {
        As[0][aCol + 0][aRow0] = f2tf32(aReg[0].x);  As[0][aCol + 1][aRow0] = f2tf32(aReg[0].y);
        As[0][aCol + 2][aRow0] = f2tf32(aReg[0].z);  As[0][aCol + 3][aRow0] = f2tf32(aReg[0].w);
        As[0][aCol + 0][aRow0 + 64] = f2tf32(aReg[1].x);  As[0][aCol + 1][aRow0 + 64] = f2tf32(aReg[1].y);
        As[0][aCol + 2][aRow0 + 64] = f2tf32(aReg[1].z);  As[0][aCol + 3][aRow0 + 64] = f2tf32(aReg[1].w);
        float4 c0, c1;
        c0.x = f2tf32(bReg[0].x); c0.y = f2tf32(bReg[0].y);
        c0.z = f2tf32(bReg[0].z); c0.w = f2tf32(bReg[0].w);
        c1.x = f2tf32(bReg[1].x); c1.y = f2tf32(bReg[1].y);
        c1.z = f2tf32(bReg[1].z); c1.w = f2tf32(bReg[1].w);
        *(float4*)&Bs[0][bK0][bCol]     = c0;
        *(float4*)&Bs[0][bK0 + 8][bCol] = c1;
    }
    __syncthreads();

    for (int kc = 0; kc < nk; kc++) {
        const int buf = kc & 1;
        const bool has = (kc + 1) < nk;
        if (has) {
            const int ko = (kc + 1) * 16;
            aReg[0] = *(const float4*)(aP0 + ko);
            aReg[1] = *(const float4*)(aP1 + ko);
            bReg[0] = *(const float4*)(bP0 + (size_t)ko * N);
            bReg[1] = *(const float4*)(bP1 + (size_t)ko * N);
        }
#pragma unroll
        for (int ks = 0; ks < 2; ks++) {
            const int km = ks * 8;
            float a[4][4], b[4][2];
#pragma unroll
            for (int mi = 0; mi < 4; mi++) {
                const int rr = wm + mi * 16 + grp;
                a[mi][0] = As[buf][km + tig][rr];
                a[mi][1] = As[buf][km + tig][rr + 8];
                a[mi][2] = As[buf][km + tig + 4][rr];
                a[mi][3] = As[buf][km + tig + 4][rr + 8];
            }
#pragma unroll
            for (int ni = 0; ni < 4; ni++) {
                const int cc = wn + ni * 8 + grp;
                b[ni][0] = Bs[buf][km + tig][cc];
                b[ni][1] = Bs[buf][km + tig + 4][cc];
            }
#pragma unroll
            for (int mi = 0; mi < 4; mi++)
#pragma unroll
                for (int ni = 0; ni < 4; ni++)
                    MMA_TF32(acc[mi][ni], a[mi], b[ni]);
        }
        if (has) {
            const int bb = buf ^ 1;
            As[bb][aCol + 0][aRow0] = f2tf32(aReg[0].x);  As[bb][aCol + 1][aRow0] = f2tf32(aReg[0].y);
            As[bb][aCol + 2][aRow0] = f2tf32(aReg[0].z);  As[bb][aCol + 3][aRow0] = f2tf32(aReg[0].w);
            As[bb][aCol + 0][aRow0 + 64] = f2tf32(aReg[1].x);  As[bb][aCol + 1][aRow0 + 64] = f2tf32(aReg[1].y);
            As[bb][aCol + 2][aRow0 + 64] = f2tf32(aReg[1].z);  As[bb][aCol + 3][aRow0 + 64] = f2tf32(aReg[1].w);
            float4 c0, c1;
            c0.x = f2tf32(bReg[0].x); c0.y = f2tf32(bReg[0].y);
            c0.z = f2tf32(bReg[0].z); c0.w = f2tf32(bReg[0].w);
            c1.x = f2tf32(bReg[1].x); c1.y = f2tf32(bReg[1].y);
            c1.z = f2tf32(bReg[1].z); c1.w = f2tf32(bReg[1].w);
            *(float4*)&Bs[bb][bK0][bCol]     = c0;
            *(float4*)&Bs[bb][bK0 + 8][bCol] = c1;
        }
        __syncthreads();
    }

#pragma unroll
    for (int ni = 0; ni < 4; ni++) {
        const int col = n0 + wn + ni * 8 + tig * 2;
        float b0 = bias ? bias[col]     : 0.f;
        float b1 = bias ? bias[col + 1] : 0.f;
#pragma unroll
        for (int mi = 0; mi < 4; mi++) {
            const int row = m0 + wm + mi * 16 + grp;
            float2 v0, v1;
            v0.x = acc[mi][ni][0] + b0;  v0.y = acc[mi][ni][1] + b1;
            v1.x = acc[mi][ni][2] + b0;  v1.y = acc[mi][ni][3] + b1;
            *(float2*)(Cm + (size_t)row * N + col)       = v0;
            *(float2*)(Cm + (size_t)(row + 8) * N + col) = v1;
        }
    }
}

// ============================================================
// transpose + tf32 round: dst[c][r] = rna(src[r][c]); R,C multiples of 32
// ============================================================
__global__ void transpose_rnd(const float* __restrict__ src, float* __restrict__ dst,
                              int R, int Cc)
{
    __shared__ float tile[32][33];
    const int bx = blockIdx.x * 32, by = blockIdx.y * 32;
    const int tx = threadIdx.x, ty = threadIdx.y;
#pragma unroll
    for (int i = 0; i < 4; i++)
        tile[ty + i * 8][tx] = src[(size_t)(by + ty + i * 8) * Cc + bx + tx];
    __syncthreads();
#pragma unroll
    for (int i = 0; i < 4; i++)
        dst[(size_t)(bx + ty + i * 8) * R + by + tx] = f2tf32(tile[tx][ty + i * 8]);
}

// x -> rna-rounded copy
__global__ void round_x(const float* __restrict__ x)
{
    size_t i = (size_t)blockIdx.x * 256 + threadIdx.x;
    float4 v = ((const float4*)x)[i];
    v.x = f2tf32(v.x); v.y = f2tf32(v.y); v.z = f2tf32(v.z); v.w = f2tf32(v.w);
    ((float4*)g_xr)[i] = v;
}

// ============================================================
// Pooled K/V
// ============================================================
__global__ void pool_kernel(const float* __restrict__ pool_w,
                            const float* __restrict__ pool_b)
{
    int idx = blockIdx.x * 256 + threadIdx.x;
    int d = idx & 31;
    int w = (idx >> 5) & 63;
    int h = (idx >> 11) & 15;
    int b = idx >> 15;
    const float* base = g_qkv + (size_t)((b * 64 + w) * 64) * QKVC + h * 32 + d;
    float sk = 0.f, sv = 0.f;
#pragma unroll 8
    for (int n = 0; n < 64; n++) {
        float pw = pool_w[n];
        sk += base[(size_t)n * QKVC + 512]  * pw;
        sv += base[(size_t)n * QKVC + 1024] * pw;
    }
    float pb = pool_b[0];
    g_Kg[idx] = sk + pb;
    g_Vg[idx] = sv + pb;
}

// ============================================================
// Combined bias
// ============================================================
__global__ void bias_comb(const float* __restrict__ lpb, const float* __restrict__ gpb,
                          const float* __restrict__ pfw, const float* __restrict__ pfb)
{
    int j = blockIdx.x * 256 + threadIdx.x;
    if (j >= 512) return;
    float s = pfb[j];
    for (int c = 0; c < 512; c++) s += lpb[c] * pfw[c * 512 + j];
    for (int c = 0; c < 512; c++) s += gpb[c] * pfw[(512 + c) * 512 + j];
    g_bc[j] = s;
}

// ============================================================
// Fused fine + coarse attention (output rna-rounded for tf32 final GEMM)
// ============================================================
__global__ __launch_bounds__(256) void attn_kernel(const float* __restrict__ lbt,
                                                   const float* __restrict__ gbt)
{
    const int head = blockIdx.x;
    const int bw   = blockIdx.y;
    const int b    = bw >> 6;
    const int t    = threadIdx.x;

    __shared__ float sq[64][33], sk[64][33], sv[64][33];
    __shared__ float S[64][65];
    __shared__ float tabL[225], tabG[225];

    for (int i = t; i < 225; i += 256) {
        tabL[i] = lbt[i * 16 + head];
        tabG[i] = gbt[i * 16 + head];
    }
    {
        const float* qbase = g_qkv + (size_t)(bw * 64) * QKVC + head * 32;
        for (int i = t; i < 512; i += 256) {
            int n = i >> 3, d = (i & 7) * 4;
            float4 q4 = *(const float4*)(qbase + (size_t)n * QKVC + d);
            float4 k4 = *(const float4*)(qbase + (size_t)n * QKVC + 512 + d);
            float4 v4 = *(const float4*)(qbase + (size_t)n * QKVC + 1024 + d);
            sq[n][d] = q4.x; sq[n][d+1] = q4.y; sq[n][d+2] = q4.z; sq[n][d+3] = q4.w;
            sk[n][d] = k4.x; sk[n][d+1] = k4.y; sk[n][d+2] = k4.z; sk[n][d+3] = k4.w;
            sv[n][d] = v4.x; sv[n][d+1] = v4.y; sv[n][d+2] = v4.z; sv[n][d+3] = v4.w;
        }
    }
    __syncthreads();

    const int n  = t >> 2;
    const int gl = t & 3;
    const int ri = n >> 3, ci = n & 7;
    const int dbase = gl * 8;

    float qr[32];
#pragma unroll
    for (int d = 0; d < 32; d++) qr[d] = sq[n][d] * 0.17677669529663687f;

    // -------- fine --------
    {
        float sc[16], mx = -1e30f;
#pragma unroll
        for (int i = 0; i < 16; i++) {
            int m = gl + i * 4;
            float a = 0.f;
#pragma unroll
            for (int d = 0; d < 32; d++) a += qr[d] * sk[m][d];
            int rj = m >> 3, cj = m & 7;
            a += tabL[(ri - rj + 7) * 15 + (ci - cj + 7)];
            sc[i] = a;
            mx = fmaxf(mx, a);
        }
        mx = fmaxf(mx, __shfl_xor_sync(0xffffffffu, mx, 1));
        mx = fmaxf(mx, __shfl_xor_sync(0xffffffffu, mx, 2));
        float sum = 0.f;
#pragma unroll
        for (int i = 0; i < 16; i++) {
            float e = expf(sc[i] - mx);
            S[n][gl + i * 4] = e;
            sum += e;
        }
        sum += __shfl_xor_sync(0xffffffffu, sum, 1);
        sum += __shfl_xor_sync(0xffffffffu, sum, 2);
        float inv = 1.f / sum;
        __syncwarp();

        float acc[8];
#pragma unroll
        for (int j = 0; j < 8; j++) acc[j] = 0.f;
        for (int m = 0; m < 64; m++) {
            float p = S[n][m];
#pragma unroll
            for (int j = 0; j < 8; j++) acc[j] += p * sv[m][dbase + j];
        }
        float* orow = g_A + (size_t)(bw * 64 + n) * 1024 + head * 32 + dbase;
#pragma unroll
        for (int j = 0; j < 8; j++) orow[j] = f2tf32(acc[j] * inv);
    }
    __syncthreads();

    {
        const float* kgb = g_Kg + (size_t)((b * 16 + head) * 64) * 32;
        const float* vgb = g_Vg + (size_t)((b * 16 + head) * 64) * 32;
        for (int i = t; i < 512; i += 256) {
            int w = i >> 3, d = (i & 7) * 4;
            float4 k4 = *(const float4*)(kgb + w * 32 + d);
            float4 v4 = *(const float4*)(vgb + w * 32 + d);
            sk[w][d] = k4.x; sk[w][d+1] = k4.y; sk[w][d+2] = k4.z; sk[w][d+3] = k4.w;
            sv[w][d] = v4.x; sv[w][d+1] = v4.y; sv[w][d+2] = v4.z; sv[w][d+3] = v4.w;
        }
    }
    __syncthreads();

    // -------- coarse --------
    {
        float sc[16], mx = -1e30f;
#pragma unroll
        for (int i = 0; i < 16; i++) {
            int w = gl + i * 4;
            float a = 0.f;
#pragma unroll
            for (int d = 0; d < 32; d++) a += qr[d] * sk[w][d];
            int wr = w >> 3, wc = w & 7;
            a += tabG[(ri - wr + 7) * 15 + (ci - wc + 7)];
            sc[i] = a;
            mx = fmaxf(mx, a);
        }
        mx = fmaxf(mx, __shfl_xor_sync(0xffffffffu, mx, 1));
        mx = fmaxf(mx, __shfl_xor_sync(0xffffffffu, mx, 2));
        float sum = 0.f;
#pragma unroll
        for (int i = 0; i < 16; i++) {
            float e = expf(sc[i] - mx);
            S[n][gl + i * 4] = e;
            sum += e;
        }
        sum += __shfl_xor_sync(0xffffffffu, sum, 1);
        sum += __shfl_xor_sync(0xffffffffu, sum, 2);
        float inv = 1.f / sum;
        __syncwarp();

        float acc[8];
#pragma unroll
        for (int j = 0; j < 8; j++) acc[j] = 0.f;
        for (int m = 0; m < 64; m++) {
            float p = S[n][m];
#pragma unroll
            for (int j = 0; j < 8; j++) acc[j] += p * sv[m][dbase + j];
        }
        float* orow = g_A + (size_t)(bw * 64 + n) * 1024 + 512 + head * 32 + dbase;
#pragma unroll
        for (int j = 0; j < 8; j++) orow[j] = f2tf32(acc[j] * inv);
    }
}

// ============================================================
// launch
// ============================================================
extern "C" void kernel_launch(void* const* d_in, const int* in_sizes, int n_in,
                              void* d_out, int out_size)
{
    (void)in_sizes; (void)n_in; (void)out_size;
    const float* x     = (const float*)d_in[0];
    const float* qkv_w = (const float*)d_in[1];
    const float* qkv_b = (const float*)d_in[2];
    const float* lbt   = (const float*)d_in[3];
    const float* gbt   = (const float*)d_in[4];
    const float* lpw   = (const float*)d_in[5];
    const float* lpb   = (const float*)d_in[6];
    const float* pw    = (const float*)d_in[7];
    const float* pb    = (const float*)d_in[8];
    const float* gpw   = (const float*)d_in[9];
    const float* gpb   = (const float*)d_in[10];
    const float* pfw   = (const float*)d_in[11];
    const float* pfb   = (const float*)d_in[12];
    float* out = (float*)d_out;

    float *gqkv, *gA, *gW, *gWT, *gqwT, *gbc, *gxr;
    cudaGetSymbolAddress((void**)&gqkv, g_qkv);
    cudaGetSymbolAddress((void**)&gA,   g_A);
    cudaGetSymbolAddress((void**)&gW,   g_W);
    cudaGetSymbolAddress((void**)&gWT,  g_WT);
    cudaGetSymbolAddress((void**)&gqwT, g_qwT);
    cudaGetSymbolAddress((void**)&gbc,  g_bc);
    cudaGetSymbolAddress((void**)&gxr,  g_xr);

    cudaFuncSetAttribute(gemm_big, cudaFuncAttributeMaxDynamicSharedMemorySize, GSMEM);

    // combined projection weight: W = vstack(Wl @ pfw_top, Wg @ pfw_bot)
    gemm_tf32<<<dim3(4, 4), 256>>>(lpw, pfw,             nullptr, gW,             512, 512, 512);
    gemm_tf32<<<dim3(4, 4), 256>>>(gpw, pfw + 512 * 512, nullptr, gW + 512 * 512, 512, 512, 512);
    bias_comb<<<2, 256>>>(lpb, gpb, pfw, pfb);
    // tf32-rounded operands for the big GEMMs
    transpose_rnd<<<dim3(512 / 32, 1024 / 32), dim3(32, 8)>>>(gW, gWT, 1024, 512);
    transpose_rnd<<<dim3(QKVC / 32, CDIM / 32), dim3(32, 8)>>>(qkv_w, gqwT, CDIM, QKVC);
    round_x<<<(ROWS * CDIM / 4) / 256, 256>>>(x);

    // QKV projection: g_qkv = xr @ qkv_w^T' + b
    gemm_big<<<dim3(QKVC / 256, ROWS / 128), 256, GSMEM>>>(gxr, gqwT, qkv_b, gqkv, ROWS, QKVC, CDIM);

    // pooled K/V
    pool_kernel<<<2048, 256>>>(pw, pb);

    // fused fine + coarse attention
    attn_kernel<<<dim3(NHEAD, BWIN), 256>>>(lbt, gbt);

    // out = [A_f | A_c] @ W + bc
    gemm_big<<<dim3(512 / 256, ROWS / 128), 256, GSMEM>>>(gA, gWT, gbc, out, ROWS, 512, 1024);
}

// round 7
// speedup vs baseline: 4.6609x; 2.2066x over previous
#include <cuda_runtime.h>
#include <cuda_fp16.h>
#include <math.h>
#include <stdint.h>

// ---------------- problem constants ----------------
#define ROWS   65536
#define CDIM   512
#define QKVC   1536
#define NHEAD  16
#define BWIN   1024
// ----------------------------------------------------

// Scratch (device globals: allocation-free)
__device__ __align__(16) float  g_qkv[(size_t)ROWS * QKVC];   // fp32 qkv
__device__ __align__(16) __half g_Ah[(size_t)ROWS * 1024];    // [fine|coarse] concat, half
__device__ __align__(16) __half g_xh[(size_t)ROWS * CDIM];    // x in half
__device__ __align__(16) float  g_Kg[16 * 16 * 64 * 32];
__device__ __align__(16) float  g_Vg[16 * 16 * 64 * 32];
__device__ __align__(16) float  g_W[1024 * 512];
__device__ __align__(16) __half g_WTh[512 * 1024];            // W^T [n][k] half
__device__ __align__(16) __half g_qwTh[QKVC * CDIM];          // qkv_w^T [n][k] half
__device__ __align__(16) float  g_bc[512];

__device__ __forceinline__ float f2tf32(float x) {
    unsigned r;
    asm("cvt.rna.tf32.f32 %0, %1;" : "=r"(r) : "f"(x));
    return __uint_as_float(r);
}
__device__ __forceinline__ uint32_t smem_u32(const void* p) {
    uint32_t a;
    asm("{ .reg .u64 t; cvta.to.shared.u64 t, %1; cvt.u32.u64 %0, t; }" : "=r"(a) : "l"(p));
    return a;
}
__device__ __forceinline__ uint32_t pack_h2(float lo, float hi) {
    __half2 h = __floats2half2_rn(lo, hi);
    return *(uint32_t*)&h;
}
#define CP_ASYNC16(dst, src) asm volatile("cp.async.cg.shared.global [%0], [%1], 16;" :: "r"(dst), "l"(src))
#define CP_COMMIT()          asm volatile("cp.async.commit_group;" ::: "memory")
#define CP_WAIT1()           asm volatile("cp.async.wait_group 1;" ::: "memory")

#define MMA_F16(acc, a0, a1, a2, a3, b0, b1) \
    asm volatile( \
        "mma.sync.aligned.m16n8k16.row.col.f32.f16.f16.f32 " \
        "{%0,%1,%2,%3},{%4,%5,%6,%7},{%8,%9},{%0,%1,%2,%3};" \
        : "+f"((acc)[0]), "+f"((acc)[1]), "+f"((acc)[2]), "+f"((acc)[3]) \
        : "r"(a0), "r"(a1), "r"(a2), "r"(a3), "r"(b0), "r"(b1))

#define MMA_TF32(acc, a, b) \
    asm volatile( \
        "mma.sync.aligned.m16n8k8.row.col.f32.tf32.tf32.f32 " \
        "{%0,%1,%2,%3},{%4,%5,%6,%7},{%8,%9},{%0,%1,%2,%3};" \
        : "+f"((acc)[0]), "+f"((acc)[1]), "+f"((acc)[2]), "+f"((acc)[3]) \
        : "r"(__float_as_uint((a)[0])), "r"(__float_as_uint((a)[1])), \
          "r"(__float_as_uint((a)[2])), "r"(__float_as_uint((a)[3])), \
          "r"(__float_as_uint((b)[0])), "r"(__float_as_uint((b)[1])))

// ============================================================
// FP16 tensor GEMM: C(fp32) = A(MxK,half) @ B^T (+bias), B [n][k] half.
// Block 128x256, 8 warps (64x64 tiles), BK=32 halves, 2-stage cp.async.
// Smem row stride 40 halves -> conflict-free half2 fragment loads.
// M%128==0, N%256==0, K%32==0.
// ============================================================
#define HSTR    40                       // halves per smem row
#define HSTG    ((128 + 256) * HSTR)     // halves per stage = 15360
#define HSMEM   (2 * HSTG * 2)           // bytes = 61440

__global__ __launch_bounds__(256) void gemm_half(
    const __half* __restrict__ A, const __half* __restrict__ B,
    const float* __restrict__ bias, float* __restrict__ C,
    int M, int N, int K)
{
    extern __shared__ __half smh[];
    const uint32_t sbu = smem_u32(smh);

    const int tid  = threadIdx.x;
    const int warp = tid >> 5, lane = tid & 31;
    const int grp  = lane >> 2, tig = lane & 3;
    const int m0 = blockIdx.y * 128;
    const int n0 = blockIdx.x * 256;
    const int wm = (warp & 1) * 64;
    const int wn = (warp >> 1) * 64;

    float acc[4][8][4];
#pragma unroll
    for (int mi = 0; mi < 4; mi++)
#pragma unroll
        for (int ni = 0; ni < 8; ni++)
#pragma unroll
            for (int r = 0; r < 4; r++) acc[mi][ni][r] = 0.f;

    const int nk = K >> 5;

    auto load_stage = [&](int buf, int kc) {
        const __half* Ab = A + (size_t)m0 * K + kc * 32;
        const __half* Bb = B + (size_t)n0 * K + kc * 32;
        const uint32_t sA = sbu + (uint32_t)(buf * HSTG) * 2;
        const uint32_t sB = sA + 128 * HSTR * 2;
        // A: 128 rows x 4 chunks(16B) = 512 cps -> 2/thread
#pragma unroll
        for (int i = 0; i < 2; i++) {
            int e = tid + i * 256;
            int row = e >> 2, ch = e & 3;
            CP_ASYNC16(sA + (uint32_t)(row * HSTR) * 2 + ch * 16,
                       Ab + (size_t)row * K + ch * 8);
        }
        // B: 256 rows -> 1024 cps -> 4/thread
#pragma unroll
        for (int i = 0; i < 4; i++) {
            int e = tid + i * 256;
            int row = e >> 2, ch = e & 3;
            CP_ASYNC16(sB + (uint32_t)(row * HSTR) * 2 + ch * 16,
                       Bb + (size_t)row * K + ch * 8);
        }
    };

    load_stage(0, 0); CP_COMMIT();
    if (nk > 1) load_stage(1, 1);
    CP_COMMIT();

    for (int kc = 0; kc < nk; kc++) {
        const int buf = kc & 1;
        CP_WAIT1();
        __syncthreads();

        const __half* sA = smh + buf * HSTG;
        const __half* sB = sA + 128 * HSTR;
#pragma unroll
        for (int ks = 0; ks < 2; ks++) {
            const int km = ks * 16 + 2 * tig;
            uint32_t a[4][4];
            uint32_t b[8][2];
#pragma unroll
            for (int mi = 0; mi < 4; mi++) {
                const int r = wm + mi * 16 + grp;
                a[mi][0] = *(const uint32_t*)(sA + r * HSTR + km);
                a[mi][1] = *(const uint32_t*)(sA + (r + 8) * HSTR + km);
                a[mi][2] = *(const uint32_t*)(sA + r * HSTR + km + 8);
                a[mi][3] = *(const uint32_t*)(sA + (r + 8) * HSTR + km + 8);
            }
#pragma unroll
            for (int ni = 0; ni < 8; ni++) {
                const int c = wn + ni * 8 + grp;
                b[ni][0] = *(const uint32_t*)(sB + c * HSTR + km);
                b[ni][1] = *(const uint32_t*)(sB + c * HSTR + km + 8);
            }
#pragma unroll
            for (int mi = 0; mi < 4; mi++)
#pragma unroll
                for (int ni = 0; ni < 8; ni++)
                    MMA_F16(acc[mi][ni], a[mi][0], a[mi][1], a[mi][2], a[mi][3],
                            b[ni][0], b[ni][1]);
        }
        __syncthreads();

        if (kc + 2 < nk) load_stage(buf, kc + 2);
        CP_COMMIT();
    }

    // ---- epilogue ----
#pragma unroll
    for (int ni = 0; ni < 8; ni++) {
        const int col = n0 + wn + ni * 8 + tig * 2;
        const float b0 = bias ? bias[col]     : 0.f;
        const float b1 = bias ? bias[col + 1] : 0.f;
#pragma unroll
        for (int mi = 0; mi < 4; mi++) {
            const int row = m0 + wm + mi * 16 + grp;
            float2 v0, v1;
            v0.x = acc[mi][ni][0] + b0;  v0.y = acc[mi][ni][1] + b1;
            v1.x = acc[mi][ni][2] + b0;  v1.y = acc[mi][ni][3] + b1;
            *(float2*)(C + (size_t)row * N + col)       = v0;
            *(float2*)(C + (size_t)(row + 8) * N + col) = v1;
        }
    }
}

// ============================================================
// tf32 mma GEMM for the two tiny 512^3 weight-prep GEMMs (B row-major [k][n])
// ============================================================
__global__ __launch_bounds__(256) void gemm_tf32(
    const float* __restrict__ A, const float* __restrict__ Bm,
    const float* __restrict__ bias, float* __restrict__ Cm,
    int M, int N, int K)
{
    __shared__ float As[2][16][132];
    __shared__ float Bs[2][16][132];

    const int t    = threadIdx.x;
    const int m0   = blockIdx.y * 128;
    const int n0   = blockIdx.x * 128;
    const int warp = t >> 5, lane = t & 31;
    const int grp  = lane >> 2, tig = lane & 3;
    const int wm   = (warp & 1) * 64;
    const int wn   = (warp >> 1) * 32;

    const int aRow0 = t >> 2;
    const int aCol  = (t & 3) * 4;
    const int bK0   = t >> 5;
    const int bCol  = (t & 31) * 4;

    const float* aP0 = A  + (size_t)(m0 + aRow0)      * K + aCol;
    const float* aP1 = A  + (size_t)(m0 + aRow0 + 64) * K + aCol;
    const float* bP0 = Bm + (size_t)bK0       * N + n0 + bCol;
    const float* bP1 = Bm + (size_t)(bK0 + 8) * N + n0 + bCol;

    float acc[4][4][4];
#pragma unroll
    for (int mi = 0; mi < 4; mi++)
#pragma unroll
        for (int ni = 0; ni < 4; ni++)
#pragma unroll
            for (int r = 0; r < 4; r++) acc[mi][ni][r] = 0.f;

    const int nk = K >> 4;
    float4 aReg[2], bReg[2];

    aReg[0] = *(const float4*)(aP0);
    aReg[1] = *(const float4*)(aP1);
    bReg[0] = *(const float4*)(bP0);
    bReg[1] = *(const float4*)(bP1);
    {
        As[0][aCol + 0][aRow0] = f2tf32(aReg[0].x);  As[0][aCol + 1][aRow0] = f2tf32(aReg[0].y);
        As[0][aCol + 2][aRow0] = f2tf32(aReg[0].z);  As[0][aCol + 3][aRow0] = f2tf32(aReg[0].w);
        As[0][aCol + 0][aRow0 + 64] = f2tf32(aReg[1].x);  As[0][aCol + 1][aRow0 + 64] = f2tf32(aReg[1].y);
        As[0][aCol + 2][aRow0 + 64] = f2tf32(aReg[1].z);  As[0][aCol + 3][aRow0 + 64] = f2tf32(aReg[1].w);
        float4 c0, c1;
        c0.x = f2tf32(bReg[0].x); c0.y = f2tf32(bReg[0].y);
        c0.z = f2tf32(bReg[0].z); c0.w = f2tf32(bReg[0].w);
        c1.x = f2tf32(bReg[1].x); c1.y = f2tf32(bReg[1].y);
        c1.z = f2tf32(bReg[1].z); c1.w = f2tf32(bReg[1].w);
        *(float4*)&Bs[0][bK0][bCol]     = c0;
        *(float4*)&Bs[0][bK0 + 8][bCol] = c1;
    }
    __syncthreads();

    for (int kc = 0; kc < nk; kc++) {
        const int buf = kc & 1;
        const bool has = (kc + 1) < nk;
        if (has) {
            const int ko = (kc + 1) * 16;
            aReg[0] = *(const float4*)(aP0 + ko);
            aReg[1] = *(const float4*)(aP1 + ko);
            bReg[0] = *(const float4*)(bP0 + (size_t)ko * N);
            bReg[1] = *(const float4*)(bP1 + (size_t)ko * N);
        }
#pragma unroll
        for (int ks = 0; ks < 2; ks++) {
            const int km = ks * 8;
            float a[4][4], b[4][2];
#pragma unroll
            for (int mi = 0; mi < 4; mi++) {
                const int rr = wm + mi * 16 + grp;
                a[mi][0] = As[buf][km + tig][rr];
                a[mi][1] = As[buf][km + tig][rr + 8];
                a[mi][2] = As[buf][km + tig + 4][rr];
                a[mi][3] = As[buf][km + tig + 4][rr + 8];
            }
#pragma unroll
            for (int ni = 0; ni < 4; ni++) {
                const int cc = wn + ni * 8 + grp;
                b[ni][0] = Bs[buf][km + tig][cc];
                b[ni][1] = Bs[buf][km + tig + 4][cc];
            }
#pragma unroll
            for (int mi = 0; mi < 4; mi++)
#pragma unroll
                for (int ni = 0; ni < 4; ni++)
                    MMA_TF32(acc[mi][ni], a[mi], b[ni]);
        }
        if (has) {
            const int bb = buf ^ 1;
            As[bb][aCol + 0][aRow0] = f2tf32(aReg[0].x);  As[bb][aCol + 1][aRow0] = f2tf32(aReg[0].y);
            As[bb][aCol + 2][aRow0] = f2tf32(aReg[0].z);  As[bb][aCol + 3][aRow0] = f2tf32(aReg[0].w);
            As[bb][aCol + 0][aRow0 + 64] = f2tf32(aReg[1].x);  As[bb][aCol + 1][aRow0 + 64] = f2tf32(aReg[1].y);
            As[bb][aCol + 2][aRow0 + 64] = f2tf32(aReg[1].z);  As[bb][aCol + 3][aRow0 + 64] = f2tf32(aReg[1].w);
            float4 c0, c1;
            c0.x = f2tf32(bReg[0].x); c0.y = f2tf32(bReg[0].y);
            c0.z = f2tf32(bReg[0].z); c0.w = f2tf32(bReg[0].w);
            c1.x = f2tf32(bReg[1].x); c1.y = f2tf32(bReg[1].y);
            c1.z = f2tf32(bReg[1].z); c1.w = f2tf32(bReg[1].w);
            *(float4*)&Bs[bb][bK0][bCol]     = c0;
            *(float4*)&Bs[bb][bK0 + 8][bCol] = c1;
        }
        __syncthreads();
    }

#pragma unroll
    for (int ni = 0; ni < 4; ni++) {
        const int col = n0 + wn + ni * 8 + tig * 2;
        float b0 = bias ? bias[col]     : 0.f;
        float b1 = bias ? bias[col + 1] : 0.f;
#pragma unroll
        for (int mi = 0; mi < 4; mi++) {
            const int row = m0 + wm + mi * 16 + grp;
            float2 v0, v1;
            v0.x = acc[mi][ni][0] + b0;  v0.y = acc[mi][ni][1] + b1;
            v1.x = acc[mi][ni][2] + b0;  v1.y = acc[mi][ni][3] + b1;
            *(float2*)(Cm + (size_t)row * N + col)       = v0;
            *(float2*)(Cm + (size_t)(row + 8) * N + col) = v1;
        }
    }
}

// ============================================================
// transpose + half round: dst(half)[c][r] = h(src[r][c]); R,C mult of 32
// ============================================================
__global__ void transpose_h(const float* __restrict__ src, __half* __restrict__ dst,
                            int R, int Cc)
{
    __shared__ float tile[32][33];
    const int bx = blockIdx.x * 32, by = blockIdx.y * 32;
    const int tx = threadIdx.x, ty = threadIdx.y;
#pragma unroll
    for (int i = 0; i < 4; i++)
        tile[ty + i * 8][tx] = src[(size_t)(by + ty + i * 8) * Cc + bx + tx];
    __syncthreads();
#pragma unroll
    for (int i = 0; i < 4; i++)
        dst[(size_t)(bx + ty + i * 8) * R + by + tx] = __float2half_rn(tile[tx][ty + i * 8]);
}

// x -> half copy
__global__ void round_xh(const float* __restrict__ x)
{
    size_t i = (size_t)blockIdx.x * 256 + threadIdx.x;
    float4 v = ((const float4*)x)[i];
    uint2 o;
    o.x = pack_h2(v.x, v.y);
    o.y = pack_h2(v.z, v.w);
    ((uint2*)g_xh)[i] = o;
}

// ============================================================
// Pooled K/V (fp32)
// ============================================================
__global__ void pool_kernel(const float* __restrict__ pool_w,
                            const float* __restrict__ pool_b)
{
    int idx = blockIdx.x * 256 + threadIdx.x;
    int d = idx & 31;
    int w = (idx >> 5) & 63;
    int h = (idx >> 11) & 15;
    int b = idx >> 15;
    const float* base = g_qkv + (size_t)((b * 64 + w) * 64) * QKVC + h * 32 + d;
    float sk = 0.f, sv = 0.f;
#pragma unroll 8
    for (int n = 0; n < 64; n++) {
        float pw = pool_w[n];
        sk += base[(size_t)n * QKVC + 512]  * pw;
        sv += base[(size_t)n * QKVC + 1024] * pw;
    }
    float pb = pool_b[0];
    g_Kg[idx] = sk + pb;
    g_Vg[idx] = sv + pb;
}

// ============================================================
// Combined bias
// ============================================================
__global__ void bias_comb(const float* __restrict__ lpb, const float* __restrict__ gpb,
                          const float* __restrict__ pfw, const float* __restrict__ pfb)
{
    int j = blockIdx.x * 256 + threadIdx.x;
    if (j >= 512) return;
    float s = pfb[j];
    for (int c = 0; c < 512; c++) s += lpb[c] * pfw[c * 512 + j];
    for (int c = 0; c < 512; c++) s += gpb[c] * pfw[(512 + c) * 512 + j];
    g_bc[j] = s;
}

// ============================================================
// Tensor-core fused attention. One block (128 thr, 4 warps) per (head, bw).
// QK^T and P.V via m16n8k16 fp16 mma; softmax fp32 on fragments.
// Output written as half directly into g_Ah (final-GEMM operand).
// ============================================================
#define SQ_STR 40   // halves (q,k rows: 32 data + 8 pad)
#define SP_STR 72   // halves (P rows / Vt rows: 64 data + 8 pad)

__global__ __launch_bounds__(128) void attn_kernel(const float* __restrict__ lbt,
                                                   const float* __restrict__ gbt)
{
    const int head = blockIdx.x;
    const int bw   = blockIdx.y;
    const int b    = bw >> 6;
    const int t    = threadIdx.x;
    const int warp = t >> 5, lane = t & 31;
    const int grp  = lane >> 2, tig = lane & 3;

    __shared__ __half sQ[64 * SQ_STR];
    __shared__ __half sK[64 * SQ_STR];
    __shared__ __half sVt[32 * SP_STR];
    __shared__ __half sP[64 * SP_STR];
    __shared__ float tabL[225], tabG[225];

    for (int i = t; i < 225; i += 128) {
        tabL[i] = lbt[i * 16 + head];
        tabG[i] = gbt[i * 16 + head];
    }
    {
        const float* qbase = g_qkv + (size_t)(bw * 64) * QKVC + head * 32;
        for (int i = t; i < 512; i += 128) {
            int n = i >> 3, d = (i & 7) * 4;
            float4 q4 = *(const float4*)(qbase + (size_t)n * QKVC + d);
            float4 k4 = *(const float4*)(qbase + (size_t)n * QKVC + 512 + d);
            float4 v4 = *(const float4*)(qbase + (size_t)n * QKVC + 1024 + d);
            const float sc = 0.17677669529663687f;
            sQ[n * SQ_STR + d + 0] = __float2half_rn(q4.x * sc);
            sQ[n * SQ_STR + d + 1] = __float2half_rn(q4.y * sc);
            sQ[n * SQ_STR + d + 2] = __float2half_rn(q4.z * sc);
            sQ[n * SQ_STR + d + 3] = __float2half_rn(q4.w * sc);
            sK[n * SQ_STR + d + 0] = __float2half_rn(k4.x);
            sK[n * SQ_STR + d + 1] = __float2half_rn(k4.y);
            sK[n * SQ_STR + d + 2] = __float2half_rn(k4.z);
            sK[n * SQ_STR + d + 3] = __float2half_rn(k4.w);
            sVt[(d + 0) * SP_STR + n] = __float2half_rn(v4.x);
            sVt[(d + 1) * SP_STR + n] = __float2half_rn(v4.y);
            sVt[(d + 2) * SP_STR + n] = __float2half_rn(v4.z);
            sVt[(d + 3) * SP_STR + n] = __float2half_rn(v4.w);
        }
    }
    __syncthreads();

    const int wrow = warp * 16;
    const int r0 = wrow + grp, r1 = r0 + 8;
    const int ri0 = r0 >> 3, ci0 = r0 & 7;
    const int ri1 = r1 >> 3, ci1 = r1 & 7;

    auto do_phase = [&](const float* tab, int outOff) {
        // ---- S = Q @ K^T (rows wrow..wrow+15, all 64 cols) ----
        float s[8][4];
#pragma unroll
        for (int ni = 0; ni < 8; ni++)
#pragma unroll
            for (int r = 0; r < 4; r++) s[ni][r] = 0.f;
#pragma unroll
        for (int ks = 0; ks < 2; ks++) {
            const int km = ks * 16 + 2 * tig;
            uint32_t a0 = *(const uint32_t*)(sQ + r0 * SQ_STR + km);
            uint32_t a1 = *(const uint32_t*)(sQ + r1 * SQ_STR + km);
            uint32_t a2 = *(const uint32_t*)(sQ + r0 * SQ_STR + km + 8);
            uint32_t a3 = *(const uint32_t*)(sQ + r1 * SQ_STR + km + 8);
#pragma unroll
            for (int ni = 0; ni < 8; ni++) {
                uint32_t b0 = *(const uint32_t*)(sK + (ni * 8 + grp) * SQ_STR + km);
                uint32_t b1 = *(const uint32_t*)(sK + (ni * 8 + grp) * SQ_STR + km + 8);
                MMA_F16(s[ni], a0, a1, a2, a3, b0, b1);
            }
        }
        // ---- bias + softmax ----
        float mx0 = -1e30f, mx1 = -1e30f;
#pragma unroll
        for (int ni = 0; ni < 8; ni++) {
            const int c = ni * 8 + 2 * tig;
            const int rj0 = c >> 3,      cj0 = c & 7;
            const int rj1 = (c + 1) >> 3, cj1 = (c + 1) & 7;
            s[ni][0] += tab[(ri0 - rj0 + 7) * 15 + (ci0 - cj0 + 7)];
            s[ni][1] += tab[(ri0 - rj1 + 7) * 15 + (ci0 - cj1 + 7)];
            s[ni][2] += tab[(ri1 - rj0 + 7) * 15 + (ci1 - cj0 + 7)];
            s[ni][3] += tab[(ri1 - rj1 + 7) * 15 + (ci1 - cj1 + 7)];
            mx0 = fmaxf(mx0, fmaxf(s[ni][0], s[ni][1]));
            mx1 = fmaxf(mx1, fmaxf(s[ni][2], s[ni][3]));
        }
        mx0 = fmaxf(mx0, __shfl_xor_sync(0xffffffffu, mx0, 1));
        mx0 = fmaxf(mx0, __shfl_xor_sync(0xffffffffu, mx0, 2));
        mx1 = fmaxf(mx1, __shfl_xor_sync(0xffffffffu, mx1, 1));
        mx1 = fmaxf(mx1, __shfl_xor_sync(0xffffffffu, mx1, 2));
        float sum0 = 0.f, sum1 = 0.f;
#pragma unroll
        for (int ni = 0; ni < 8; ni++) {
            s[ni][0] = __expf(s[ni][0] - mx0);
            s[ni][1] = __expf(s[ni][1] - mx0);
            s[ni][2] = __expf(s[ni][2] - mx1);
            s[ni][3] = __expf(s[ni][3] - mx1);
            sum0 += s[ni][0] + s[ni][1];
            sum1 += s[ni][2] + s[ni][3];
        }
        sum0 += __shfl_xor_sync(0xffffffffu, sum0, 1);
        sum0 += __shfl_xor_sync(0xffffffffu, sum0, 2);
        sum1 += __shfl_xor_sync(0xffffffffu, sum1, 1);
        sum1 += __shfl_xor_sync(0xffffffffu, sum1, 2);
        const float inv0 = 1.f / sum0, inv1 = 1.f / sum1;
#pragma unroll
        for (int ni = 0; ni < 8; ni++) {
            const int c = ni * 8 + 2 * tig;
            *(uint32_t*)(sP + r0 * SP_STR + c) = pack_h2(s[ni][0] * inv0, s[ni][1] * inv0);
            *(uint32_t*)(sP + r1 * SP_STR + c) = pack_h2(s[ni][2] * inv1, s[ni][3] * inv1);
        }
        // ---- O = P @ V (16 rows x 32 cols) ----  (sP rows are warp-private)
        float o[4][4];
#pragma unroll
        for (int ni = 0; ni < 4; ni++)
#pragma unroll
            for (int r = 0; r < 4; r++) o[ni][r] = 0.f;
#pragma unroll
        for (int ks = 0; ks < 4; ks++) {
            const int km = ks * 16 + 2 * tig;
            uint32_t a0 = *(const uint32_t*)(sP + r0 * SP_STR + km);
            uint32_t a1 = *(const uint32_t*)(sP + r1 * SP_STR + km);
            uint32_t a2 = *(const uint32_t*)(sP + r0 * SP_STR + km + 8);
            uint32_t a3 = *(const uint32_t*)(sP + r1 * SP_STR + km + 8);
#pragma unroll
            for (int ni = 0; ni < 4; ni++) {
                uint32_t b0 = *(const uint32_t*)(sVt + (ni * 8 + grp) * SP_STR + km);
                uint32_t b1 = *(const uint32_t*)(sVt + (ni * 8 + grp) * SP_STR + km + 8);
                MMA_F16(o[ni], a0, a1, a2, a3, b0, b1);
            }
        }
        __half* o0 = g_Ah + (size_t)(bw * 64 + r0) * 1024 + outOff + head * 32;
        __half* o1 = g_Ah + (size_t)(bw * 64 + r1) * 1024 + outOff + head * 32;
#pragma unroll
        for (int ni = 0; ni < 4; ni++) {
            const int c = ni * 8 + 2 * tig;
            *(uint32_t*)(o0 + c) = pack_h2(o[ni][0], o[ni][1]);
            *(uint32_t*)(o1 + c) = pack_h2(o[ni][2], o[ni][3]);
        }
    };

    do_phase(tabL, 0);
    __syncthreads();   // all warps done reading sK/sVt

    {
        const float* kgb = g_Kg + (size_t)((b * 16 + head) * 64) * 32;
        const float* vgb = g_Vg + (size_t)((b * 16 + head) * 64) * 32;
        for (int i = t; i < 512; i += 128) {
            int w = i >> 3, d = (i & 7) * 4;
            float4 k4 = *(const float4*)(kgb + w * 32 + d);
            float4 v4 = *(const float4*)(vgb + w * 32 + d);
            sK[w * SQ_STR + d + 0] = __float2half_rn(k4.x);
            sK[w * SQ_STR + d + 1] = __float2half_rn(k4.y);
            sK[w * SQ_STR + d + 2] = __float2half_rn(k4.z);
            sK[w * SQ_STR + d + 3] = __float2half_rn(k4.w);
            sVt[(d + 0) * SP_STR + w] = __float2half_rn(v4.x);
            sVt[(d + 1) * SP_STR + w] = __float2half_rn(v4.y);
            sVt[(d + 2) * SP_STR + w] = __float2half_rn(v4.z);
            sVt[(d + 3) * SP_STR + w] = __float2half_rn(v4.w);
        }
    }
    __syncthreads();

    do_phase(tabG, 512);
}

// ============================================================
// launch
// ============================================================
extern "C" void kernel_launch(void* const* d_in, const int* in_sizes, int n_in,
                              void* d_out, int out_size)
{
    (void)in_sizes; (void)n_in; (void)out_size;
    const float* x     = (const float*)d_in[0];
    const float* qkv_w = (const float*)d_in[1];
    const float* qkv_b = (const float*)d_in[2];
    const float* lbt   = (const float*)d_in[3];
    const float* gbt   = (const float*)d_in[4];
    const float* lpw   = (const float*)d_in[5];
    const float* lpb   = (const float*)d_in[6];
    const float* pw    = (const float*)d_in[7];
    const float* pb    = (const float*)d_in[8];
    const float* gpw   = (const float*)d_in[9];
    const float* gpb   = (const float*)d_in[10];
    const float* pfw   = (const float*)d_in[11];
    const float* pfb   = (const float*)d_in[12];
    float* out = (float*)d_out;

    float *gqkv, *gW, *gbc;
    __half *gAh, *gxh, *gWTh, *gqwTh;
    cudaGetSymbolAddress((void**)&gqkv,  g_qkv);
    cudaGetSymbolAddress((void**)&gAh,   g_Ah);
    cudaGetSymbolAddress((void**)&gxh,   g_xh);
    cudaGetSymbolAddress((void**)&gW,    g_W);
    cudaGetSymbolAddress((void**)&gWTh,  g_WTh);
    cudaGetSymbolAddress((void**)&gqwTh, g_qwTh);
    cudaGetSymbolAddress((void**)&gbc,   g_bc);

    cudaFuncSetAttribute(gemm_half, cudaFuncAttributeMaxDynamicSharedMemorySize, HSMEM);

    // combined projection weight: W = vstack(Wl @ pfw_top, Wg @ pfw_bot)
    gemm_tf32<<<dim3(4, 4), 256>>>(lpw, pfw,             nullptr, gW,             512, 512, 512);
    gemm_tf32<<<dim3(4, 4), 256>>>(gpw, pfw + 512 * 512, nullptr, gW + 512 * 512, 512, 512, 512);
    bias_comb<<<2, 256>>>(lpb, gpb, pfw, pfb);
    // half operands for the big GEMMs
    transpose_h<<<dim3(512 / 32, 1024 / 32), dim3(32, 8)>>>(gW, gWTh, 1024, 512);
    transpose_h<<<dim3(QKVC / 32, CDIM / 32), dim3(32, 8)>>>(qkv_w, gqwTh, CDIM, QKVC);
    round_xh<<<(ROWS * CDIM / 4) / 256, 256>>>(x);

    // QKV projection: g_qkv = x_h @ qkv_w^T' + b
    gemm_half<<<dim3(QKVC / 256, ROWS / 128), 256, HSMEM>>>(gxh, gqwTh, qkv_b, gqkv, ROWS, QKVC, CDIM);

    // pooled K/V
    pool_kernel<<<2048, 256>>>(pw, pb);

    // fused fine + coarse attention (tensor cores) -> g_Ah (half)
    attn_kernel<<<dim3(NHEAD, BWIN), 128>>>(lbt, gbt);

    // out = [A_f | A_c] @ W + bc
    gemm_half<<<dim3(512 / 256, ROWS / 128), 256, HSMEM>>>(gAh, gWTh, gbc, out, ROWS, 512, 1024);
}

// round 8
// speedup vs baseline: 5.7023x; 1.2234x over previous
#include <cuda_runtime.h>
#include <cuda_fp16.h>
#include <math.h>
#include <stdint.h>

// ---------------- problem constants ----------------
#define ROWS   65536
#define CDIM   512
#define QKVC   1536
#define NHEAD  16
#define BWIN   1024
// ----------------------------------------------------

// Scratch (device globals: allocation-free)
__device__ __align__(16) __half g_qkvh[(size_t)ROWS * QKVC];  // qkv in half (q pre-scaled)
__device__ __align__(16) __half g_Ah[(size_t)ROWS * 1024];    // [fine|coarse] concat, half
__device__ __align__(16) __half g_xh[(size_t)ROWS * CDIM];    // x in half
__device__ __align__(16) float  g_Kg[16 * 16 * 64 * 32];
__device__ __align__(16) float  g_Vg[16 * 16 * 64 * 32];
__device__ __align__(16) float  g_W[1024 * 512];
__device__ __align__(16) __half g_WTh[512 * 1024];            // W^T [n][k] half
__device__ __align__(16) __half g_qwTh[QKVC * CDIM];          // qkv_w^T [n][k] half (q rows scaled)
__device__ __align__(16) float  g_qb[QKVC];                   // qkv_b (q part scaled)
__device__ __align__(16) float  g_bc[512];

__device__ __forceinline__ float f2tf32(float x) {
    unsigned r;
    asm("cvt.rna.tf32.f32 %0, %1;" : "=r"(r) : "f"(x));
    return __uint_as_float(r);
}
__device__ __forceinline__ uint32_t smem_u32(const void* p) {
    uint32_t a;
    asm("{ .reg .u64 t; cvta.to.shared.u64 t, %1; cvt.u32.u64 %0, t; }" : "=r"(a) : "l"(p));
    return a;
}
__device__ __forceinline__ uint32_t pack_h2(float lo, float hi) {
    __half2 h = __floats2half2_rn(lo, hi);
    return *(uint32_t*)&h;
}
#define CP_ASYNC16(dst, src) asm volatile("cp.async.cg.shared.global [%0], [%1], 16;" :: "r"(dst), "l"(src))
#define CP_COMMIT()          asm volatile("cp.async.commit_group;" ::: "memory")
#define CP_WAIT1()           asm volatile("cp.async.wait_group 1;" ::: "memory")

#define MMA_F16(acc, a0, a1, a2, a3, b0, b1) \
    asm volatile( \
        "mma.sync.aligned.m16n8k16.row.col.f32.f16.f16.f32 " \
        "{%0,%1,%2,%3},{%4,%5,%6,%7},{%8,%9},{%0,%1,%2,%3};" \
        : "+f"((acc)[0]), "+f"((acc)[1]), "+f"((acc)[2]), "+f"((acc)[3]) \
        : "r"(a0), "r"(a1), "r"(a2), "r"(a3), "r"(b0), "r"(b1))

#define MMA_TF32(acc, a, b) \
    asm volatile( \
        "mma.sync.aligned.m16n8k8.row.col.f32.tf32.tf32.f32 " \
        "{%0,%1,%2,%3},{%4,%5,%6,%7},{%8,%9},{%0,%1,%2,%3};" \
        : "+f"((acc)[0]), "+f"((acc)[1]), "+f"((acc)[2]), "+f"((acc)[3]) \
        : "r"(__float_as_uint((a)[0])), "r"(__float_as_uint((a)[1])), \
          "r"(__float_as_uint((a)[2])), "r"(__float_as_uint((a)[3])), \
          "r"(__float_as_uint((b)[0])), "r"(__float_as_uint((b)[1])))

#define LDSM4(r0, r1, r2, r3, addr) \
    asm volatile("ldmatrix.sync.aligned.m8n8.x4.shared.b16 {%0,%1,%2,%3}, [%4];" \
        : "=r"(r0), "=r"(r1), "=r"(r2), "=r"(r3) : "r"(addr))

// ============================================================
// FP16 tensor GEMM: C = A(MxK,half) @ B^T (+bias), B [n][k] half.
// Block 128x128 (128 thr, 4 warps of 64x64), BK=32, 2-stage cp.async,
// ldmatrix.x4 fragment loads. 2 CTAs/SM. M%128==0, N%128==0, K%32==0.
// HOUT: write half (QKV) else fp32 (final output).
// ============================================================
#define HSTR   40                        // halves per smem row
#define HROWB  80                        // bytes per smem row
#define HBOFF  (128 * HROWB)             // B region offset in stage (10240 B)
#define HSTGB  (256 * HROWB)             // stage bytes (20480)
#define HSMEM  (2 * HSTGB)               // 40960 bytes (< 48KB default)

template<bool HOUT>
__global__ __launch_bounds__(128, 2) void gemm_h(
    const __half* __restrict__ A, const __half* __restrict__ B,
    const float* __restrict__ bias, void* __restrict__ Cv,
    int M, int N, int K)
{
    extern __shared__ __half smh[];
    const uint32_t sbu = smem_u32(smh);

    const int tid  = threadIdx.x;
    const int warp = tid >> 5, lane = tid & 31;
    const int grp  = lane >> 2, tig = lane & 3;
    const int m0 = blockIdx.y * 128;
    const int n0 = blockIdx.x * 128;
    const int wm = (warp & 1) * 64;
    const int wn = (warp >> 1) * 64;

    // ldmatrix lane address bases (bytes, within stage)
    const uint32_t aBase = (uint32_t)((wm + (lane & 15)) * HROWB + ((lane >> 4) * 16));
    const uint32_t bBase = (uint32_t)(HBOFF +
        (wn + (lane & 7) + ((lane >> 4) & 1) * 8) * HROWB + (((lane >> 3) & 1) * 16));

    float acc[4][8][4];
#pragma unroll
    for (int mi = 0; mi < 4; mi++)
#pragma unroll
        for (int ni = 0; ni < 8; ni++)
#pragma unroll
            for (int r = 0; r < 4; r++) acc[mi][ni][r] = 0.f;

    const int nk = K >> 5;

    auto load_stage = [&](int buf, int kc) {
        const __half* Ab = A + (size_t)m0 * K + kc * 32;
        const __half* Bb = B + (size_t)n0 * K + kc * 32;
        const uint32_t sA = sbu + (uint32_t)buf * HSTGB;
        const uint32_t sB = sA + HBOFF;
        // A: 128 rows x 4 16B-chunks = 512 cps -> 4/thread; same for B
#pragma unroll
        for (int i = 0; i < 4; i++) {
            int e = tid + i * 128;
            int row = e >> 2, ch = e & 3;
            CP_ASYNC16(sA + (uint32_t)row * HROWB + ch * 16, Ab + (size_t)row * K + ch * 8);
            CP_ASYNC16(sB + (uint32_t)row * HROWB + ch * 16, Bb + (size_t)row * K + ch * 8);
        }
    };

    load_stage(0, 0); CP_COMMIT();
    if (nk > 1) load_stage(1, 1);
    CP_COMMIT();

    for (int kc = 0; kc < nk; kc++) {
        const int buf = kc & 1;
        CP_WAIT1();
        __syncthreads();

        const uint32_t sg = sbu + (uint32_t)buf * HSTGB;
#pragma unroll
        for (int ks = 0; ks < 2; ks++) {
            const uint32_t ko = ks * 32;   // 16 halves
            uint32_t a[4][4], b[8][2];
#pragma unroll
            for (int mi = 0; mi < 4; mi++)
                LDSM4(a[mi][0], a[mi][1], a[mi][2], a[mi][3],
                      sg + aBase + mi * (16 * HROWB) + ko);
#pragma unroll
            for (int np = 0; np < 4; np++)
                LDSM4(b[2 * np][0], b[2 * np][1], b[2 * np + 1][0], b[2 * np + 1][1],
                      sg + bBase + np * (16 * HROWB) + ko);
#pragma unroll
            for (int mi = 0; mi < 4; mi++)
#pragma unroll
                for (int ni = 0; ni < 8; ni++)
                    MMA_F16(acc[mi][ni], a[mi][0], a[mi][1], a[mi][2], a[mi][3],
                            b[ni][0], b[ni][1]);
        }
        __syncthreads();

        if (kc + 2 < nk) load_stage(buf, kc + 2);
        CP_COMMIT();
    }

    // ---- epilogue ----
#pragma unroll
    for (int ni = 0; ni < 8; ni++) {
        const int col = n0 + wn + ni * 8 + tig * 2;
        const float b0 = bias ? bias[col]     : 0.f;
        const float b1 = bias ? bias[col + 1] : 0.f;
#pragma unroll
        for (int mi = 0; mi < 4; mi++) {
            const int row = m0 + wm + mi * 16 + grp;
            if (HOUT) {
                __half* C = (__half*)Cv;
                *(uint32_t*)(C + (size_t)row * N + col) =
                    pack_h2(acc[mi][ni][0] + b0, acc[mi][ni][1] + b1);
                *(uint32_t*)(C + (size_t)(row + 8) * N + col) =
                    pack_h2(acc[mi][ni][2] + b0, acc[mi][ni][3] + b1);
            } else {
                float* C = (float*)Cv;
                float2 v0, v1;
                v0.x = acc[mi][ni][0] + b0;  v0.y = acc[mi][ni][1] + b1;
                v1.x = acc[mi][ni][2] + b0;  v1.y = acc[mi][ni][3] + b1;
                *(float2*)(C + (size_t)row * N + col)       = v0;
                *(float2*)(C + (size_t)(row + 8) * N + col) = v1;
            }
        }
    }
}

// ============================================================
// tf32 mma GEMM for the two tiny 512^3 weight-prep GEMMs (B row-major [k][n])
// ============================================================
__global__ __launch_bounds__(256) void gemm_tf32(
    const float* __restrict__ A, const float* __restrict__ Bm,
    const float* __restrict__ bias, float* __restrict__ Cm,
    int M, int N, int K)
{
    __shared__ float As[2][16][132];
    __shared__ float Bs[2][16][132];

    const int t    = threadIdx.x;
    const int m0   = blockIdx.y * 128;
    const int n0   = blockIdx.x * 128;
    const int warp = t >> 5, lane = t & 31;
    const int grp  = lane >> 2, tig = lane & 3;
    const int wm   = (warp & 1) * 64;
    const int wn   = (warp >> 1) * 32;

    const int aRow0 = t >> 2;
    const int aCol  = (t & 3) * 4;
    const int bK0   = t >> 5;
    const int bCol  = (t & 31) * 4;

    const float* aP0 = A  + (size_t)(m0 + aRow0)      * K + aCol;
    const float* aP1 = A  + (size_t)(m0 + aRow0 + 64) * K + aCol;
    const float* bP0 = Bm + (size_t)bK0       * N + n0 + bCol;
    const float* bP1 = Bm + (size_t)(bK0 + 8) * N + n0 + bCol;

    float acc[4][4][4];
#pragma unroll
    for (int mi = 0; mi < 4; mi++)
#pragma unroll
        for (int ni = 0; ni < 4; ni++)
#pragma unroll
            for (int r = 0; r < 4; r++) acc[mi][ni][r] = 0.f;

    const int nk = K >> 4;
    float4 aReg[2], bReg[2];

    aReg[0] = *(const float4*)(aP0);
    aReg[1] = *(const float4*)(aP1);
    bReg[0] = *(const float4*)(bP0);
    bReg[1] = *(const float4*)(bP1);
    {
        As[0][aCol + 0][aRow0] = f2tf32(aReg[0].x);  As[0][aCol + 1][aRow0] = f2tf32(aReg[0].y);
        As[0][aCol + 2][aRow0] = f2tf32(aReg[0].z);  As[0][aCol + 3][aRow0] = f2tf32(aReg[0].w);
        As[0][aCol + 0][aRow0 + 64] = f2tf32(aReg[1].x);  As[0][aCol + 1][aRow0 + 64] = f2tf32(aReg[1].y);
        As[0][aCol + 2][aRow0 + 64] = f2tf32(aReg[1].z);  As[0][aCol + 3][aRow0 + 64] = f2tf32(aReg[1].w);
        float4 c0, c1;
        c0.x = f2tf32(bReg[0].x); c0.y = f2tf32(bReg[0].y);
        c0.z = f2tf32(bReg[0].z); c0.w = f2tf32(bReg[0].w);
        c1.x = f2tf32(bReg[1].x); c1.y = f2tf32(bReg[1].y);
        c1.z = f2tf32(bReg[1].z); c1.w = f2tf32(bReg[1].w);
        *(float4*)&Bs[0][bK0][bCol]     = c0;
        *(float4*)&Bs[0][bK0 + 8][bCol] = c1;
    }
    __syncthreads();

    for (int kc = 0; kc < nk; kc++) {
        const int buf = kc & 1;
        const bool has = (kc + 1) < nk;
        if (has) {
            const int ko = (kc + 1) * 16;
            aReg[0] = *(const float4*)(aP0 + ko);
            aReg[1] = *(const float4*)(aP1 + ko);
            bReg[0] = *(const float4*)(bP0 + (size_t)ko * N);
            bReg[1] = *(const float4*)(bP1 + (size_t)ko * N);
        }
#pragma unroll
        for (int ks = 0; ks < 2; ks++) {
            const int km = ks * 8;
            float a[4][4], b[4][2];
#pragma unroll
            for (int mi = 0; mi < 4; mi++) {
                const int rr = wm + mi * 16 + grp;
                a[mi][0] = As[buf][km + tig][rr];
                a[mi][1] = As[buf][km + tig][rr + 8];
                a[mi][2] = As[buf][km + tig + 4][rr];
                a[mi][3] = As[buf][km + tig + 4][rr + 8];
            }
#pragma unroll
            for (int ni = 0; ni < 4; ni++) {
                const int cc = wn + ni * 8 + grp;
                b[ni][0] = Bs[buf][km + tig][cc];
                b[ni][1] = Bs[buf][km + tig + 4][cc];
            }
#pragma unroll
            for (int mi = 0; mi < 4; mi++)
#pragma unroll
                for (int ni = 0; ni < 4; ni++)
                    MMA_TF32(acc[mi][ni], a[mi], b[ni]);
        }
        if (has) {
            const int bb = buf ^ 1;
            As[bb][aCol + 0][aRow0] = f2tf32(aReg[0].x);  As[bb][aCol + 1][aRow0] = f2tf32(aReg[0].y);
            As[bb][aCol + 2][aRow0] = f2tf32(aReg[0].z);  As[bb][aCol + 3][aRow0] = f2tf32(aReg[0].w);
            As[bb][aCol + 0][aRow0 + 64] = f2tf32(aReg[1].x);  As[bb][aCol + 1][aRow0 + 64] = f2tf32(aReg[1].y);
            As[bb][aCol + 2][aRow0 + 64] = f2tf32(aReg[1].z);  As[bb][aCol + 3][aRow0 + 64] = f2tf32(aReg[1].w);
            float4 c0, c1;
            c0.x = f2tf32(bReg[0].x); c0.y = f2tf32(bReg[0].y);
            c0.z = f2tf32(bReg[0].z); c0.w = f2tf32(bReg[0].w);
            c1.x = f2tf32(bReg[1].x); c1.y = f2tf32(bReg[1].y);
            c1.z = f2tf32(bReg[1].z); c1.w = f2tf32(bReg[1].w);
            *(float4*)&Bs[bb][bK0][bCol]     = c0;
            *(float4*)&Bs[bb][bK0 + 8][bCol] = c1;
        }
        __syncthreads();
    }

#pragma unroll
    for (int ni = 0; ni < 4; ni++) {
        const int col = n0 + wn + ni * 8 + tig * 2;
        float b0 = bias ? bias[col]     : 0.f;
        float b1 = bias ? bias[col + 1] : 0.f;
#pragma unroll
        for (int mi = 0; mi < 4; mi++) {
            const int row = m0 + wm + mi * 16 + grp;
            float2 v0, v1;
            v0.x = acc[mi][ni][0] + b0;  v0.y = acc[mi][ni][1] + b1;
            v1.x = acc[mi][ni][2] + b0;  v1.y = acc[mi][ni][3] + b1;
            *(float2*)(Cm + (size_t)row * N + col)       = v0;
            *(float2*)(Cm + (size_t)(row + 8) * N + col) = v1;
        }
    }
}

// ============================================================
// transpose + half round: dst(half)[c][r] = h(src[r][c] * (c<scaleRows ? s : 1))
// ============================================================
__global__ void transpose_h(const float* __restrict__ src, __half* __restrict__ dst,
                            int R, int Cc, int scaleRows, float s)
{
    __shared__ float tile[32][33];
    const int bx = blockIdx.x * 32, by = blockIdx.y * 32;
    const int tx = threadIdx.x, ty = threadIdx.y;
#pragma unroll
    for (int i = 0; i < 4; i++)
        tile[ty + i * 8][tx] = src[(size_t)(by + ty + i * 8) * Cc + bx + tx];
    __syncthreads();
#pragma unroll
    for (int i = 0; i < 4; i++) {
        int drow = bx + ty + i * 8;
        float v = tile[tx][ty + i * 8];
        if (drow < scaleRows) v *= s;
        dst[(size_t)drow * R + by + tx] = __float2half_rn(v);
    }
}

// qkv bias with q part pre-scaled
__global__ void scale_qb(const float* __restrict__ qkv_b)
{
    int j = blockIdx.x * 256 + threadIdx.x;
    if (j < QKVC) g_qb[j] = qkv_b[j] * (j < 512 ? 0.17677669529663687f : 1.0f);
}

// x -> half copy
__global__ void round_xh(const float* __restrict__ x)
{
    size_t i = (size_t)blockIdx.x * 256 + threadIdx.x;
    float4 v = ((const float4*)x)[i];
    uint2 o;
    o.x = pack_h2(v.x, v.y);
    o.y = pack_h2(v.z, v.w);
    ((uint2*)g_xh)[i] = o;
}

// ============================================================
// Pooled K/V (half source, fp32 accumulation)
// ============================================================
__global__ void pool_kernel(const float* __restrict__ pool_w,
                            const float* __restrict__ pool_b)
{
    int idx = blockIdx.x * 256 + threadIdx.x;
    int d = idx & 31;
    int w = (idx >> 5) & 63;
    int h = (idx >> 11) & 15;
    int b = idx >> 15;
    const __half* base = g_qkvh + (size_t)((b * 64 + w) * 64) * QKVC + h * 32 + d;
    float sk = 0.f, sv = 0.f;
#pragma unroll 8
    for (int n = 0; n < 64; n++) {
        float pw = pool_w[n];
        sk += __half2float(base[(size_t)n * QKVC + 512])  * pw;
        sv += __half2float(base[(size_t)n * QKVC + 1024]) * pw;
    }
    float pb = pool_b[0];
    g_Kg[idx] = sk + pb;
    g_Vg[idx] = sv + pb;
}

// ============================================================
// Combined bias
// ============================================================
__global__ void bias_comb(const float* __restrict__ lpb, const float* __restrict__ gpb,
                          const float* __restrict__ pfw, const float* __restrict__ pfb)
{
    int j = blockIdx.x * 256 + threadIdx.x;
    if (j >= 512) return;
    float s = pfb[j];
    for (int c = 0; c < 512; c++) s += lpb[c] * pfw[c * 512 + j];
    for (int c = 0; c < 512; c++) s += gpb[c] * pfw[(512 + c) * 512 + j];
    g_bc[j] = s;
}

// ============================================================
// Tensor-core fused attention. One block (128 thr, 4 warps) per (head, bw).
// q pre-scaled in g_qkvh; loads are plain half copies.
// ============================================================
#define SQ_STR 40   // halves
#define SP_STR 72   // halves

__global__ __launch_bounds__(128) void attn_kernel(const float* __restrict__ lbt,
                                                   const float* __restrict__ gbt)
{
    const int head = blockIdx.x;
    const int bw   = blockIdx.y;
    const int b    = bw >> 6;
    const int t    = threadIdx.x;
    const int warp = t >> 5, lane = t & 31;
    const int grp  = lane >> 2, tig = lane & 3;

    __shared__ __half sQ[64 * SQ_STR];
    __shared__ __half sK[64 * SQ_STR];
    __shared__ __half sVt[32 * SP_STR];
    __shared__ __half sP[64 * SP_STR];
    __shared__ float tabL[225], tabG[225];

    for (int i = t; i < 225; i += 128) {
        tabL[i] = lbt[i * 16 + head];
        tabG[i] = gbt[i * 16 + head];
    }
    {
        const __half* qbase = g_qkvh + (size_t)(bw * 64) * QKVC + head * 32;
        for (int i = t; i < 512; i += 128) {
            int n = i >> 3, d = (i & 7) * 4;
            uint2 q4 = *(const uint2*)(qbase + (size_t)n * QKVC + d);
            uint2 k4 = *(const uint2*)(qbase + (size_t)n * QKVC + 512 + d);
            uint2 v4 = *(const uint2*)(qbase + (size_t)n * QKVC + 1024 + d);
            *(uint32_t*)(sQ + n * SQ_STR + d)     = q4.x;
            *(uint32_t*)(sQ + n * SQ_STR + d + 2) = q4.y;
            *(uint32_t*)(sK + n * SQ_STR + d)     = k4.x;
            *(uint32_t*)(sK + n * SQ_STR + d + 2) = k4.y;
            __half2 v01 = *(__half2*)&v4.x;
            __half2 v23 = *(__half2*)&v4.y;
            sVt[(d + 0) * SP_STR + n] = __low2half(v01);
            sVt[(d + 1) * SP_STR + n] = __high2half(v01);
            sVt[(d + 2) * SP_STR + n] = __low2half(v23);
            sVt[(d + 3) * SP_STR + n] = __high2half(v23);
        }
    }
    __syncthreads();

    const int wrow = warp * 16;
    const int r0 = wrow + grp, r1 = r0 + 8;
    const int ri0 = r0 >> 3, ci0 = r0 & 7;
    const int ri1 = r1 >> 3, ci1 = r1 & 7;

    auto do_phase = [&](const float* tab, int outOff) {
        float s[8][4];
#pragma unroll
        for (int ni = 0; ni < 8; ni++)
#pragma unroll
            for (int r = 0; r < 4; r++) s[ni][r] = 0.f;
#pragma unroll
        for (int ks = 0; ks < 2; ks++) {
            const int km = ks * 16 + 2 * tig;
            uint32_t a0 = *(const uint32_t*)(sQ + r0 * SQ_STR + km);
            uint32_t a1 = *(const uint32_t*)(sQ + r1 * SQ_STR + km);
            uint32_t a2 = *(const uint32_t*)(sQ + r0 * SQ_STR + km + 8);
            uint32_t a3 = *(const uint32_t*)(sQ + r1 * SQ_STR + km + 8);
#pragma unroll
            for (int ni = 0; ni < 8; ni++) {
                uint32_t b0 = *(const uint32_t*)(sK + (ni * 8 + grp) * SQ_STR + km);
                uint32_t b1 = *(const uint32_t*)(sK + (ni * 8 + grp) * SQ_STR + km + 8);
                MMA_F16(s[ni], a0, a1, a2, a3, b0, b1);
            }
        }
        float mx0 = -1e30f, mx1 = -1e30f;
#pragma unroll
        for (int ni = 0; ni < 8; ni++) {
            const int c = ni * 8 + 2 * tig;
            const int rj0 = c >> 3,       cj0 = c & 7;
            const int rj1 = (c + 1) >> 3, cj1 = (c + 1) & 7;
            s[ni][0] += tab[(ri0 - rj0 + 7) * 15 + (ci0 - cj0 + 7)];
            s[ni][1] += tab[(ri0 - rj1 + 7) * 15 + (ci0 - cj1 + 7)];
            s[ni][2] += tab[(ri1 - rj0 + 7) * 15 + (ci1 - cj0 + 7)];
            s[ni][3] += tab[(ri1 - rj1 + 7) * 15 + (ci1 - cj1 + 7)];
            mx0 = fmaxf(mx0, fmaxf(s[ni][0], s[ni][1]));
            mx1 = fmaxf(mx1, fmaxf(s[ni][2], s[ni][3]));
        }
        mx0 = fmaxf(mx0, __shfl_xor_sync(0xffffffffu, mx0, 1));
        mx0 = fmaxf(mx0, __shfl_xor_sync(0xffffffffu, mx0, 2));
        mx1 = fmaxf(mx1, __shfl_xor_sync(0xffffffffu, mx1, 1));
        mx1 = fmaxf(mx1, __shfl_xor_sync(0xffffffffu, mx1, 2));
        float sum0 = 0.f, sum1 = 0.f;
#pragma unroll
        for (int ni = 0; ni < 8; ni++) {
            s[ni][0] = __expf(s[ni][0] - mx0);
            s[ni][1] = __expf(s[ni][1] - mx0);
            s[ni][2] = __expf(s[ni][2] - mx1);
            s[ni][3] = __expf(s[ni][3] - mx1);
            sum0 += s[ni][0] + s[ni][1];
            sum1 += s[ni][2] + s[ni][3];
        }
        sum0 += __shfl_xor_sync(0xffffffffu, sum0, 1);
        sum0 += __shfl_xor_sync(0xffffffffu, sum0, 2);
        sum1 += __shfl_xor_sync(0xffffffffu, sum1, 1);
        sum1 += __shfl_xor_sync(0xffffffffu, sum1, 2);
        const float inv0 = 1.f / sum0, inv1 = 1.f / sum1;
#pragma unroll
        for (int ni = 0; ni < 8; ni++) {
            const int c = ni * 8 + 2 * tig;
            *(uint32_t*)(sP + r0 * SP_STR + c) = pack_h2(s[ni][0] * inv0, s[ni][1] * inv0);
            *(uint32_t*)(sP + r1 * SP_STR + c) = pack_h2(s[ni][2] * inv1, s[ni][3] * inv1);
        }
        float o[4][4];
#pragma unroll
        for (int ni = 0; ni < 4; ni++)
#pragma unroll
            for (int r = 0; r < 4; r++) o[ni][r] = 0.f;
#pragma unroll
        for (int ks = 0; ks < 4; ks++) {
            const int km = ks * 16 + 2 * tig;
            uint32_t a0 = *(const uint32_t*)(sP + r0 * SP_STR + km);
            uint32_t a1 = *(const uint32_t*)(sP + r1 * SP_STR + km);
            uint32_t a2 = *(const uint32_t*)(sP + r0 * SP_STR + km + 8);
            uint32_t a3 = *(const uint32_t*)(sP + r1 * SP_STR + km + 8);
#pragma unroll
            for (int ni = 0; ni < 4; ni++) {
                uint32_t b0 = *(const uint32_t*)(sVt + (ni * 8 + grp) * SP_STR + km);
                uint32_t b1 = *(const uint32_t*)(sVt + (ni * 8 + grp) * SP_STR + km + 8);
                MMA_F16(o[ni], a0, a1, a2, a3, b0, b1);
            }
        }
        __half* o0 = g_Ah + (size_t)(bw * 64 + r0) * 1024 + outOff + head * 32;
        __half* o1 = g_Ah + (size_t)(bw * 64 + r1) * 1024 + outOff + head * 32;
#pragma unroll
        for (int ni = 0; ni < 4; ni++) {
            const int c = ni * 8 + 2 * tig;
            *(uint32_t*)(o0 + c) = pack_h2(o[ni][0], o[ni][1]);
            *(uint32_t*)(o1 + c) = pack_h2(o[ni][2], o[ni][3]);
        }
    };

    do_phase(tabL, 0);
    __syncthreads();

    {
        const float* kgb = g_Kg + (size_t)((b * 16 + head) * 64) * 32;
        const float* vgb = g_Vg + (size_t)((b * 16 + head) * 64) * 32;
        for (int i = t; i < 512; i += 128) {
            int w = i >> 3, d = (i & 7) * 4;
            float4 k4 = *(const float4*)(kgb + w * 32 + d);
            float4 v4 = *(const float4*)(vgb + w * 32 + d);
            *(uint32_t*)(sK + w * SQ_STR + d)     = pack_h2(k4.x, k4.y);
            *(uint32_t*)(sK + w * SQ_STR + d + 2) = pack_h2(k4.z, k4.w);
            sVt[(d + 0) * SP_STR + w] = __float2half_rn(v4.x);
            sVt[(d + 1) * SP_STR + w] = __float2half_rn(v4.y);
            sVt[(d + 2) * SP_STR + w] = __float2half_rn(v4.z);
            sVt[(d + 3) * SP_STR + w] = __float2half_rn(v4.w);
        }
    }
    __syncthreads();

    do_phase(tabG, 512);
}

// ============================================================
// launch
// ============================================================
extern "C" void kernel_launch(void* const* d_in, const int* in_sizes, int n_in,
                              void* d_out, int out_size)
{
    (void)in_sizes; (void)n_in; (void)out_size;
    const float* x     = (const float*)d_in[0];
    const float* qkv_w = (const float*)d_in[1];
    const float* qkv_b = (const float*)d_in[2];
    const float* lbt   = (const float*)d_in[3];
    const float* gbt   = (const float*)d_in[4];
    const float* lpw   = (const float*)d_in[5];
    const float* lpb   = (const float*)d_in[6];
    const float* pw    = (const float*)d_in[7];
    const float* pb    = (const float*)d_in[8];
    const float* gpw   = (const float*)d_in[9];
    const float* gpb   = (const float*)d_in[10];
    const float* pfw   = (const float*)d_in[11];
    const float* pfb   = (const float*)d_in[12];
    float* out = (float*)d_out;

    float *gW, *gbc, *gqb;
    __half *gqkvh, *gAh, *gxh, *gWTh, *gqwTh;
    cudaGetSymbolAddress((void**)&gqkvh, g_qkvh);
    cudaGetSymbolAddress((void**)&gAh,   g_Ah);
    cudaGetSymbolAddress((void**)&gxh,   g_xh);
    cudaGetSymbolAddress((void**)&gW,    g_W);
    cudaGetSymbolAddress((void**)&gWTh,  g_WTh);
    cudaGetSymbolAddress((void**)&gqwTh, g_qwTh);
    cudaGetSymbolAddress((void**)&gbc,   g_bc);
    cudaGetSymbolAddress((void**)&gqb,   g_qb);

    // combined projection weight: W = vstack(Wl @ pfw_top, Wg @ pfw_bot)
    gemm_tf32<<<dim3(4, 4), 256>>>(lpw, pfw,             nullptr, gW,             512, 512, 512);
    gemm_tf32<<<dim3(4, 4), 256>>>(gpw, pfw + 512 * 512, nullptr, gW + 512 * 512, 512, 512, 512);
    bias_comb<<<2, 256>>>(lpb, gpb, pfw, pfb);
    // half operands (q rows of qkv weight/bias pre-scaled by 1/sqrt(hd))
    transpose_h<<<dim3(512 / 32, 1024 / 32), dim3(32, 8)>>>(gW, gWTh, 1024, 512, 0, 1.f);
    transpose_h<<<dim3(QKVC / 32, CDIM / 32), dim3(32, 8)>>>(qkv_w, gqwTh, CDIM, QKVC,
                                                             512, 0.17677669529663687f);
    scale_qb<<<6, 256>>>(qkv_b);
    round_xh<<<(ROWS * CDIM / 4) / 256, 256>>>(x);

    // QKV projection: g_qkvh = x_h @ qkv_w^T' + qb   (half output)
    gemm_h<true><<<dim3(QKVC / 128, ROWS / 128), 128, HSMEM>>>(
        gxh, gqwTh, gqb, gqkvh, ROWS, QKVC, CDIM);

    // pooled K/V
    pool_kernel<<<2048, 256>>>(pw, pb);

    // fused fine + coarse attention (tensor cores) -> g_Ah (half)
    attn_kernel<<<dim3(NHEAD, BWIN), 128>>>(lbt, gbt);

    // out = [A_f | A_c] @ W + bc   (fp32 output)
    gemm_h<false><<<dim3(512 / 128, ROWS / 128), 128, HSMEM>>>(
        gAh, gWTh, gbc, out, ROWS, 512, 1024);
}